// round 1
// baseline (speedup 1.0000x reference)
#include <cuda_runtime.h>
#include <cstdint>

#define L   16
#define NB  128
#define NC  128
#define NE  10
#define NT3 816     // sorted triples a<=b<=d
#define NT2 136     // sorted pairs a<=b
#define COLS3 128   // padded column count for order-3 (23 + 3*33 = 122 real)
#define COLS2 24    // padded column count for order-2 (4 + 3*6 = 22 real)
#define NWY 68      // wy columns: 23 + 33 + 4 + 6 + 1 + 1

// Scratch (device globals: allocation-free)
__device__ float g_Us3[NT3 * COLS3];     // symmetrized order-3 coeffs [t][j]
__device__ float g_Us2[NT2 * COLS2];     // symmetrized order-2 coeffs [t][j]
__device__ float g_Us1[L * 4];           // order-1 coeffs [a][col]
__device__ float g_wy[NB * NWY * NC];    // wy[b][jw][c]

// ---------------- packed f32x2 helpers ----------------
__device__ __forceinline__ unsigned long long pack2(float v) {
    unsigned long long r;
    asm("mov.b64 %0, {%1, %1};" : "=l"(r) : "f"(v));
    return r;
}
__device__ __forceinline__ void unpack2(unsigned long long v, float& lo, float& hi) {
    asm("mov.b64 {%0, %1}, %2;" : "=f"(lo), "=f"(hi) : "l"(v));
}
__device__ __forceinline__ void fma2(unsigned long long& d, unsigned long long a,
                                     unsigned long long b) {
    asm("fma.rn.f32x2 %0, %1, %2, %0;" : "+l"(d) : "l"(a), "l"(b));
}

// ---------------- K0a: symmetrize order-3 U ----------------
// grid = NT3 blocks, 128 threads. Block t handles sorted triple t; thread j = column.
__global__ void k_sym3(const float* __restrict__ U3_0e, const float* __restrict__ U3_1o) {
    int t = blockIdx.x;
    int A = 0, B2 = 0, D = 0;
    {
        int rem = t;
        bool done = false;
        for (int i = 0; i < L && !done; i++) {
            for (int j = i; j < L; j++) {
                int cnt = L - j;
                if (rem < cnt) { A = i; B2 = j; D = j + rem; done = true; break; }
                rem -= cnt;
            }
        }
    }
    int P[6][3] = {{A,B2,D},{A,D,B2},{B2,A,D},{B2,D,A},{D,A,B2},{D,B2,A}};
    int j = threadIdx.x;
    float val = 0.f;
    if (j < 122) {
        for (int i = 0; i < 6; i++) {
            bool dup = false;
            for (int q = 0; q < i; q++)
                if (P[q][0] == P[i][0] && P[q][1] == P[i][1] && P[q][2] == P[i][2]) dup = true;
            if (dup) continue;
            int p0 = P[i][0], p1 = P[i][1], p2 = P[i][2];
            if (j < 23) {
                val += U3_0e[((p0 * L + p1) * L + p2) * 23 + j];
            } else {
                int w = (j - 23) / 33, k = (j - 23) % 33;
                val += U3_1o[(((w * L + p0) * L + p1) * L + p2) * 33 + k];
            }
        }
    }
    g_Us3[t * COLS3 + j] = val;
}

// ---------------- K0b: symmetrize order-2 U ----------------
__global__ void k_sym2(const float* __restrict__ U2_0e, const float* __restrict__ U2_1o) {
    int t = blockIdx.x;
    int A = 0, B2 = 0;
    {
        int rem = t;
        for (int i = 0; i < L; i++) {
            int cnt = L - i;
            if (rem < cnt) { A = i; B2 = i + rem; break; }
            rem -= cnt;
        }
    }
    int j = threadIdx.x;
    if (j >= COLS2) return;
    float val = 0.f;
    if (j < 22) {
        if (j < 4) {
            val = U2_0e[(A * L + B2) * 4 + j];
            if (A != B2) val += U2_0e[(B2 * L + A) * 4 + j];
        } else {
            int w = (j - 4) / 6, k = (j - 4) % 6;
            val = U2_1o[((w * L + A) * L + B2) * 6 + k];
            if (A != B2) val += U2_1o[((w * L + B2) * L + A) * 6 + k];
        }
    }
    g_Us2[t * COLS2 + j] = val;
}

// ---------------- K0c: order-1 U ----------------
__global__ void k_sym1(const float* __restrict__ U1_0e, const float* __restrict__ U1_1o) {
    int id = threadIdx.x;
    if (id >= L * 4) return;
    int a = id >> 2, col = id & 3;
    float val = (col == 0) ? U1_0e[a] : U1_1o[(col - 1) * L + a];
    g_Us1[a * 4 + col] = val;
}

// ---------------- K1: wy[b][jw][c] = sum_e w[e][k][c] * y[b][e] ----------------
__global__ void k_wy(const float* __restrict__ y,
                     const float* __restrict__ w3_0e, const float* __restrict__ w3_1o,
                     const float* __restrict__ w2_0e, const float* __restrict__ w2_1o,
                     const float* __restrict__ w1_0e, const float* __restrict__ w1_1o) {
    int jw = blockIdx.x, b = blockIdx.y, c = threadIdx.x;
    const float* wsrc; int K, k;
    if (jw < 23)      { wsrc = w3_0e; K = 23; k = jw; }
    else if (jw < 56) { wsrc = w3_1o; K = 33; k = jw - 23; }
    else if (jw < 60) { wsrc = w2_0e; K = 4;  k = jw - 56; }
    else if (jw < 66) { wsrc = w2_1o; K = 6;  k = jw - 60; }
    else if (jw == 66){ wsrc = w1_0e; K = 1;  k = 0; }
    else              { wsrc = w1_1o; K = 1;  k = 0; }
    float acc = 0.f;
#pragma unroll
    for (int e = 0; e < NE; e++)
        acc = fmaf(wsrc[(e * K + k) * NC + c], y[b * NE + e], acc);
    g_wy[(b * NWY + jw) * NC + c] = acc;
}

// ---------------- K2: main fused polynomial kernel ----------------
// grid = NB blocks (one atom b); block = (128 channels) x (2 column-groups).
// Each thread owns one channel; accumulators pack column pairs as f32x2.
__global__ void __launch_bounds__(256, 1)
k_main(const float* __restrict__ x, float* __restrict__ out) {
    extern __shared__ float sm[];
    const int c = threadIdx.x;
    const int g = threadIdx.y;
    const int b = blockIdx.x;

    float* mybuf  = sm + g * (NT3 * 32);        // this group's coeff staging
    float* outPart = sm + 2 * (NT3 * 32);       // [2][128][4]

    // Load X = x[b, c, 0..15]
    float X[L];
    {
        const float4* xp = (const float4*)(x + (b * NC + c) * L);
#pragma unroll
        for (int q = 0; q < 4; q++) {
            float4 v = xp[q];
            X[4*q+0] = v.x; X[4*q+1] = v.y; X[4*q+2] = v.z; X[4*q+3] = v.w;
        }
    }

    float o0 = 0.f, o1 = 0.f, o2 = 0.f, o3 = 0.f;
    const float* wyb = g_wy + (b * NWY) * NC + c;

    // ===== order-3: each group does 2 chunks of 32 columns =====
    for (int it = 0; it < 2; it++) {
        const int colbase = (g * 2 + it) * 32;
        // cooperative stage: 816 rows x 32 floats (128B per row) into smem
        {
            float4* d4 = (float4*)mybuf;
            for (int idx = c; idx < NT3 * 8; idx += NC) {
                int row = idx >> 3, c4 = idx & 7;
                d4[idx] = ((const float4*)(g_Us3 + row * COLS3 + colbase))[c4];
            }
        }
        __syncthreads();

        unsigned long long acc[16];
#pragma unroll
        for (int w = 0; w < 16; w++) acc[w] = 0ull;

        const unsigned long long* rowp = (const unsigned long long*)mybuf;
        for (int a = 0; a < L; a++) {
            float xa = X[a];
            for (int bb = a; bb < L; bb++) {
                float p = xa * X[bb];
                for (int d = bb; d < L; d++) {
                    unsigned long long m2 = pack2(p * X[d]);
#pragma unroll
                    for (int w = 0; w < 16; w++) fma2(acc[w], m2, rowp[w]);
                    rowp += 16;
                }
            }
        }

        // epilogue: weight P_j by wy and route to output slot
#pragma unroll
        for (int w = 0; w < 16; w++) {
            float lo, hi;
            unpack2(acc[w], lo, hi);
            int jbase = colbase + 2 * w;
#pragma unroll
            for (int h = 0; h < 2; h++) {
                int j = jbase + h;
                float v = (h == 0) ? lo : hi;
                if (j < 122) {
                    int tgt, wyc;
                    if (j < 23) { tgt = 0; wyc = j; }
                    else {
                        int wq = (j - 23) / 33;
                        tgt = 1 + wq;
                        wyc = 23 + (j - 23 - wq * 33);
                    }
                    float contrib = v * wyb[wyc * NC];
                    if (tgt == 0) o0 += contrib;
                    else if (tgt == 1) o1 += contrib;
                    else if (tgt == 2) o2 += contrib;
                    else o3 += contrib;
                }
            }
        }
        __syncthreads();
    }

    // ===== order-2: group g handles 12 columns (6 packed pairs) =====
    {
        const int colbase = g * 12;
        for (int idx = c; idx < NT2 * 12; idx += NC) {
            int row = idx / 12, cc = idx - row * 12;
            mybuf[idx] = g_Us2[row * COLS2 + colbase + cc];
        }
        __syncthreads();

        unsigned long long acc[6];
#pragma unroll
        for (int w = 0; w < 6; w++) acc[w] = 0ull;

        const unsigned long long* rowp = (const unsigned long long*)mybuf;
        for (int a = 0; a < L; a++) {
            float xa = X[a];
            for (int bb = a; bb < L; bb++) {
                unsigned long long m2 = pack2(xa * X[bb]);
#pragma unroll
                for (int w = 0; w < 6; w++) fma2(acc[w], m2, rowp[w]);
                rowp += 6;
            }
        }
#pragma unroll
        for (int w = 0; w < 6; w++) {
            float lo, hi;
            unpack2(acc[w], lo, hi);
            int jbase = colbase + 2 * w;
#pragma unroll
            for (int h = 0; h < 2; h++) {
                int j = jbase + h;
                float v = (h == 0) ? lo : hi;
                if (j < 22) {
                    int tgt, wyc;
                    if (j < 4) { tgt = 0; wyc = 56 + j; }
                    else {
                        int wq = (j - 4) / 6;
                        tgt = 1 + wq;
                        wyc = 60 + (j - 4 - wq * 6);
                    }
                    float contrib = v * wyb[wyc * NC];
                    if (tgt == 0) o0 += contrib;
                    else if (tgt == 1) o1 += contrib;
                    else if (tgt == 2) o2 += contrib;
                    else o3 += contrib;
                }
            }
        }
    }

    // ===== order-1 (group 1 only) =====
    if (g == 1) {
        float P0 = 0.f, P1 = 0.f, P2 = 0.f, P3 = 0.f;
#pragma unroll
        for (int a = 0; a < L; a++) {
            float xa = X[a];
            P0 = fmaf(g_Us1[a * 4 + 0], xa, P0);
            P1 = fmaf(g_Us1[a * 4 + 1], xa, P1);
            P2 = fmaf(g_Us1[a * 4 + 2], xa, P2);
            P3 = fmaf(g_Us1[a * 4 + 3], xa, P3);
        }
        float wv66 = wyb[66 * NC], wv67 = wyb[67 * NC];
        o0 += P0 * wv66;
        o1 += P1 * wv67;
        o2 += P2 * wv67;
        o3 += P3 * wv67;
    }

    // ===== reduce the two groups, write output =====
    outPart[(g * NC + c) * 4 + 0] = o0;
    outPart[(g * NC + c) * 4 + 1] = o1;
    outPart[(g * NC + c) * 4 + 2] = o2;
    outPart[(g * NC + c) * 4 + 3] = o3;
    __syncthreads();
    if (g == 0) {
        float t0 = outPart[c * 4 + 0] + outPart[(NC + c) * 4 + 0];
        float t1 = outPart[c * 4 + 1] + outPart[(NC + c) * 4 + 1];
        float t2 = outPart[c * 4 + 2] + outPart[(NC + c) * 4 + 2];
        float t3 = outPart[c * 4 + 3] + outPart[(NC + c) * 4 + 3];
        float* ob = out + b * 512;
        ob[c] = t0;                    // out0[b,c]
        ob[128 + 3 * c + 0] = t1;      // out1[b,c,w] reshaped c-major
        ob[128 + 3 * c + 1] = t2;
        ob[128 + 3 * c + 2] = t3;
    }
}

static const size_t SMEM_BYTES = (2 * (size_t)NT3 * 32 + 2 * NC * 4) * sizeof(float); // 212,992

extern "C" void kernel_launch(void* const* d_in, const int* in_sizes, int n_in,
                              void* d_out, int out_size) {
    const float* x      = (const float*)d_in[0];
    const float* y      = (const float*)d_in[1];
    const float* U1_0e  = (const float*)d_in[2];
    const float* U2_0e  = (const float*)d_in[3];
    const float* U3_0e  = (const float*)d_in[4];
    const float* U1_1o  = (const float*)d_in[5];
    const float* U2_1o  = (const float*)d_in[6];
    const float* U3_1o  = (const float*)d_in[7];
    const float* w1_0e  = (const float*)d_in[8];
    const float* w2_0e  = (const float*)d_in[9];
    const float* w3_0e  = (const float*)d_in[10];
    const float* w1_1o  = (const float*)d_in[11];
    const float* w2_1o  = (const float*)d_in[12];
    const float* w3_1o  = (const float*)d_in[13];
    float* out = (float*)d_out;

    cudaFuncSetAttribute(k_main, cudaFuncAttributeMaxDynamicSharedMemorySize,
                         (int)SMEM_BYTES);

    k_sym3<<<NT3, 128>>>(U3_0e, U3_1o);
    k_sym2<<<NT2, 32>>>(U2_0e, U2_1o);
    k_sym1<<<1, 64>>>(U1_0e, U1_1o);
    k_wy<<<dim3(NWY, NB), NC>>>(y, w3_0e, w3_1o, w2_0e, w2_1o, w1_0e, w1_1o);
    k_main<<<NB, dim3(NC, 2), SMEM_BYTES>>>(x, out);
}

// round 2
// speedup vs baseline: 1.0068x; 1.0068x over previous
#include <cuda_runtime.h>

#define L   16
#define NB  128
#define NC  128
#define NE  10
#define NT3 816     // sorted triples a<=b<=d
#define NT2 136     // sorted pairs a<=b
#define COLS3 128   // padded column count order-3 (122 real = 23 + 3*33)
#define COLS2 24    // padded column count order-2 (22 real = 4 + 3*6)
#define NWY 68      // wy columns: 23 + 33 + 4 + 6 + 1 + 1

// Scratch (device globals: allocation-free)
__device__ float g_Us3[NT3 * COLS3];
__device__ float g_Us2[NT2 * COLS2];
__device__ float g_Us1[L * 4];
__device__ float g_wy[NB * NWY * NC];

// ---------------- packed f32x2 helpers ----------------
__device__ __forceinline__ unsigned long long pack2(float v) {
    unsigned long long r;
    asm("mov.b64 %0, {%1, %1};" : "=l"(r) : "f"(v));
    return r;
}
__device__ __forceinline__ void unpack2(unsigned long long v, float& lo, float& hi) {
    asm("mov.b64 {%0, %1}, %2;" : "=f"(lo), "=f"(hi) : "l"(v));
}
__device__ __forceinline__ void fma2(unsigned long long& d, unsigned long long a,
                                     unsigned long long b) {
    asm("fma.rn.f32x2 %0, %1, %2, %0;" : "+l"(d) : "l"(a), "l"(b));
}

// ---------------- K0: merged symmetrization ----------------
// blocks [0,816): order-3 triple t; [816,952): order-2 pair; 952: order-1.
__global__ void k_setup(const float* __restrict__ U1_0e, const float* __restrict__ U2_0e,
                        const float* __restrict__ U3_0e, const float* __restrict__ U1_1o,
                        const float* __restrict__ U2_1o, const float* __restrict__ U3_1o) {
    int blk = blockIdx.x;
    int j = threadIdx.x;
    if (blk < NT3) {
        int t = blk;
        int A = 0, B2 = 0, D = 0;
        {
            int rem = t;
            bool done = false;
            for (int i = 0; i < L && !done; i++) {
                for (int q = i; q < L; q++) {
                    int cnt = L - q;
                    if (rem < cnt) { A = i; B2 = q; D = q + rem; done = true; break; }
                    rem -= cnt;
                }
            }
        }
        int P[6][3] = {{A,B2,D},{A,D,B2},{B2,A,D},{B2,D,A},{D,A,B2},{D,B2,A}};
        float val = 0.f;
        if (j < 122) {
            for (int i = 0; i < 6; i++) {
                bool dup = false;
                for (int q = 0; q < i; q++)
                    if (P[q][0] == P[i][0] && P[q][1] == P[i][1] && P[q][2] == P[i][2]) dup = true;
                if (dup) continue;
                int p0 = P[i][0], p1 = P[i][1], p2 = P[i][2];
                if (j < 23) {
                    val += U3_0e[((p0 * L + p1) * L + p2) * 23 + j];
                } else {
                    int w = (j - 23) / 33, k = (j - 23) % 33;
                    val += U3_1o[(((w * L + p0) * L + p1) * L + p2) * 33 + k];
                }
            }
        }
        g_Us3[t * COLS3 + j] = val;
    } else if (blk < NT3 + NT2) {
        int t = blk - NT3;
        if (j >= COLS2) return;
        int A = 0, B2 = 0;
        {
            int rem = t;
            for (int i = 0; i < L; i++) {
                int cnt = L - i;
                if (rem < cnt) { A = i; B2 = i + rem; break; }
                rem -= cnt;
            }
        }
        float val = 0.f;
        if (j < 22) {
            if (j < 4) {
                val = U2_0e[(A * L + B2) * 4 + j];
                if (A != B2) val += U2_0e[(B2 * L + A) * 4 + j];
            } else {
                int w = (j - 4) / 6, k = (j - 4) % 6;
                val = U2_1o[((w * L + A) * L + B2) * 6 + k];
                if (A != B2) val += U2_1o[((w * L + B2) * L + A) * 6 + k];
            }
        }
        g_Us2[t * COLS2 + j] = val;
    } else {
        if (j >= L * 4) return;
        int a = j >> 2, col = j & 3;
        g_Us1[a * 4 + col] = (col == 0) ? U1_0e[a] : U1_1o[(col - 1) * L + a];
    }
}

// ---------------- K1: wy[b][jw][c] = sum_e w[e][k][c] * y[b][e] ----------------
// grid = NB blocks (one atom), 256 threads.
__global__ void k_wy(const float* __restrict__ y,
                     const float* __restrict__ w3_0e, const float* __restrict__ w3_1o,
                     const float* __restrict__ w2_0e, const float* __restrict__ w2_1o,
                     const float* __restrict__ w1_0e, const float* __restrict__ w1_1o) {
    int b = blockIdx.x;
    __shared__ float ys[NE];
    if (threadIdx.x < NE) ys[threadIdx.x] = y[b * NE + threadIdx.x];
    __syncthreads();
    for (int idx = threadIdx.x; idx < NWY * NC; idx += blockDim.x) {
        int jw = idx >> 7, c = idx & 127;
        const float* wsrc; int K, k;
        if (jw < 23)       { wsrc = w3_0e; K = 23; k = jw; }
        else if (jw < 56)  { wsrc = w3_1o; K = 33; k = jw - 23; }
        else if (jw < 60)  { wsrc = w2_0e; K = 4;  k = jw - 56; }
        else if (jw < 66)  { wsrc = w2_1o; K = 6;  k = jw - 60; }
        else if (jw == 66) { wsrc = w1_0e; K = 1;  k = 0; }
        else               { wsrc = w1_1o; K = 1;  k = 0; }
        float acc = 0.f;
#pragma unroll
        for (int e = 0; e < NE; e++)
            acc = fmaf(wsrc[(e * K + k) * NC + c], ys[e], acc);
        g_wy[(b * NWY + jw) * NC + c] = acc;
    }
}

// ---------------- K2: main fused polynomial kernel ----------------
// grid = NB (one atom per block); block = 128 channels x 2 column-groups.
// Shared layout (floats): Xs[128*17] | stage[2][816*32] | outPart[2*128*4]
#define XS_STRIDE 17
#define XS_FLOATS (NC * XS_STRIDE)          // 2176
#define ST_FLOATS (NT3 * 32)                // 26112 per group
#define SM_FLOATS (XS_FLOATS + 2 * ST_FLOATS + 2 * NC * 4)

__global__ void __launch_bounds__(256, 1)
k_main(const float* __restrict__ x, float* __restrict__ out) {
    extern __shared__ float sm[];
    const int c = threadIdx.x;
    const int g = threadIdx.y;
    const int b = blockIdx.x;

    float* Xs      = sm;
    float* mybuf   = sm + XS_FLOATS + g * ST_FLOATS;
    float* outPart = sm + XS_FLOATS + 2 * ST_FLOATS;

    // Load X = x[b, c, :] into padded smem (group 0 only writes)
    if (g == 0) {
        const float4* xp = (const float4*)(x + (b * NC + c) * L);
#pragma unroll
        for (int q = 0; q < 4; q++) {
            float4 v = xp[q];
            Xs[c * XS_STRIDE + 4 * q + 0] = v.x;
            Xs[c * XS_STRIDE + 4 * q + 1] = v.y;
            Xs[c * XS_STRIDE + 4 * q + 2] = v.z;
            Xs[c * XS_STRIDE + 4 * q + 3] = v.w;
        }
    }
    const int cc = c * XS_STRIDE;

    float o0 = 0.f, o1 = 0.f, o2 = 0.f, o3 = 0.f;
    const float* wyb = g_wy + (b * NWY) * NC + c;

    // ===== order-3: each group does 2 chunks of 32 columns =====
#pragma unroll
    for (int it = 0; it < 2; it++) {
        const int colbase = (g * 2 + it) * 32;
        // cooperative stage: 816 rows x 32 floats into this group's slab
        {
            float4* d4 = (float4*)mybuf;
            const float4* s4 = (const float4*)g_Us3 + (colbase >> 2);
            for (int idx = c; idx < NT3 * 8; idx += NC) {
                int row = idx >> 3, q = idx & 7;
                d4[idx] = s4[row * (COLS3 >> 2) + q];
            }
        }
        __syncthreads();

        unsigned long long acc[16];
#pragma unroll
        for (int w = 0; w < 16; w++) acc[w] = 0ull;

        const ulonglong2* rowp = (const ulonglong2*)mybuf;
        for (int a = 0; a < L; a++) {
            float xa = Xs[cc + a];
            for (int bb = a; bb < L; bb++) {
                float p = xa * Xs[cc + bb];
                for (int d = bb; d < L; d++) {
                    unsigned long long m2 = pack2(p * Xs[cc + d]);
#pragma unroll
                    for (int w = 0; w < 8; w++) {
                        ulonglong2 q = rowp[w];
                        fma2(acc[2 * w],     m2, q.x);
                        fma2(acc[2 * w + 1], m2, q.y);
                    }
                    rowp += 8;
                }
            }
        }

        // epilogue: weight each column by its wy and route to output slot
#pragma unroll
        for (int w = 0; w < 16; w++) {
            float lo, hi;
            unpack2(acc[w], lo, hi);
#pragma unroll
            for (int h = 0; h < 2; h++) {
                int j = colbase + 2 * w + h;
                float v = (h == 0) ? lo : hi;
                if (j < 122) {
                    int tgt, wyc;
                    if (j < 23) { tgt = 0; wyc = j; }
                    else {
                        int wq = (j - 23) / 33;
                        tgt = 1 + wq;
                        wyc = 23 + (j - 23 - wq * 33);
                    }
                    float contrib = v * wyb[wyc * NC];
                    if (tgt == 0) o0 += contrib;
                    else if (tgt == 1) o1 += contrib;
                    else if (tgt == 2) o2 += contrib;
                    else o3 += contrib;
                }
            }
        }
        __syncthreads();   // group slab may be restaged next iteration
    }

    // ===== order-2: group g handles 12 columns (6 packed pairs) =====
    {
        const int colbase = g * 12;
        for (int idx = c; idx < NT2 * 12; idx += NC) {
            int row = idx / 12, q = idx - row * 12;
            mybuf[idx] = g_Us2[row * COLS2 + colbase + q];
        }
        __syncthreads();

        unsigned long long acc2[6];
#pragma unroll
        for (int w = 0; w < 6; w++) acc2[w] = 0ull;

        const ulonglong2* rp = (const ulonglong2*)mybuf;
        for (int a = 0; a < L; a++) {
            float xa = Xs[cc + a];
            for (int bb = a; bb < L; bb++) {
                unsigned long long m2 = pack2(xa * Xs[cc + bb]);
#pragma unroll
                for (int w = 0; w < 3; w++) {
                    ulonglong2 q = rp[w];
                    fma2(acc2[2 * w],     m2, q.x);
                    fma2(acc2[2 * w + 1], m2, q.y);
                }
                rp += 3;
            }
        }
#pragma unroll
        for (int w = 0; w < 6; w++) {
            float lo, hi;
            unpack2(acc2[w], lo, hi);
#pragma unroll
            for (int h = 0; h < 2; h++) {
                int j = colbase + 2 * w + h;
                float v = (h == 0) ? lo : hi;
                if (j < 22) {
                    int tgt, wyc;
                    if (j < 4) { tgt = 0; wyc = 56 + j; }
                    else {
                        int wq = (j - 4) / 6;
                        tgt = 1 + wq;
                        wyc = 60 + (j - 4 - wq * 6);
                    }
                    float contrib = v * wyb[wyc * NC];
                    if (tgt == 0) o0 += contrib;
                    else if (tgt == 1) o1 += contrib;
                    else if (tgt == 2) o2 += contrib;
                    else o3 += contrib;
                }
            }
        }
    }

    // ===== order-1 (group 1 only) =====
    if (g == 1) {
        float P0 = 0.f, P1 = 0.f, P2 = 0.f, P3 = 0.f;
#pragma unroll
        for (int a = 0; a < L; a++) {
            float xa = Xs[cc + a];
            P0 = fmaf(g_Us1[a * 4 + 0], xa, P0);
            P1 = fmaf(g_Us1[a * 4 + 1], xa, P1);
            P2 = fmaf(g_Us1[a * 4 + 2], xa, P2);
            P3 = fmaf(g_Us1[a * 4 + 3], xa, P3);
        }
        float wv66 = wyb[66 * NC], wv67 = wyb[67 * NC];
        o0 += P0 * wv66;
        o1 += P1 * wv67;
        o2 += P2 * wv67;
        o3 += P3 * wv67;
    }

    // ===== reduce the two groups, write output =====
    outPart[(g * NC + c) * 4 + 0] = o0;
    outPart[(g * NC + c) * 4 + 1] = o1;
    outPart[(g * NC + c) * 4 + 2] = o2;
    outPart[(g * NC + c) * 4 + 3] = o3;
    __syncthreads();
    if (g == 0) {
        float t0 = outPart[c * 4 + 0] + outPart[(NC + c) * 4 + 0];
        float t1 = outPart[c * 4 + 1] + outPart[(NC + c) * 4 + 1];
        float t2 = outPart[c * 4 + 2] + outPart[(NC + c) * 4 + 2];
        float t3 = outPart[c * 4 + 3] + outPart[(NC + c) * 4 + 3];
        float* ob = out + b * 512;
        ob[c] = t0;                    // out0[b,c]
        ob[128 + 3 * c + 0] = t1;      // out1[b, c*3 + w]
        ob[128 + 3 * c + 1] = t2;
        ob[128 + 3 * c + 2] = t3;
    }
}

static const size_t SMEM_BYTES = (size_t)SM_FLOATS * sizeof(float);   // 221,696 B

extern "C" void kernel_launch(void* const* d_in, const int* in_sizes, int n_in,
                              void* d_out, int out_size) {
    const float* x      = (const float*)d_in[0];
    const float* y      = (const float*)d_in[1];
    const float* U1_0e  = (const float*)d_in[2];
    const float* U2_0e  = (const float*)d_in[3];
    const float* U3_0e  = (const float*)d_in[4];
    const float* U1_1o  = (const float*)d_in[5];
    const float* U2_1o  = (const float*)d_in[6];
    const float* U3_1o  = (const float*)d_in[7];
    const float* w1_0e  = (const float*)d_in[8];
    const float* w2_0e  = (const float*)d_in[9];
    const float* w3_0e  = (const float*)d_in[10];
    const float* w1_1o  = (const float*)d_in[11];
    const float* w2_1o  = (const float*)d_in[12];
    const float* w3_1o  = (const float*)d_in[13];
    float* out = (float*)d_out;

    cudaFuncSetAttribute(k_main, cudaFuncAttributeMaxDynamicSharedMemorySize,
                         (int)SMEM_BYTES);

    k_setup<<<NT3 + NT2 + 1, 128>>>(U1_0e, U2_0e, U3_0e, U1_1o, U2_1o, U3_1o);
    k_wy<<<NB, 256>>>(y, w3_0e, w3_1o, w2_0e, w2_1o, w1_0e, w1_1o);
    k_main<<<NB, dim3(NC, 2), SMEM_BYTES>>>(x, out);
}

// round 4
// speedup vs baseline: 1.0113x; 1.0045x over previous
#include <cuda_runtime.h>

#define L   16
#define NB  128
#define NC  128
#define NE  10
#define NT3 816
#define NT2 136
#define COLS3 128   // padded (122 real = 23 + 3*33)
#define COLS2 24    // padded (22 real = 4 + 3*6)
#define NWY 68
#define CH  102     // triples per staged chunk
#define NCHUNK 8    // CH * NCHUNK = 816

typedef unsigned long long ull;

__device__ float g_Us3[NT3 * COLS3];
__device__ float g_Us2[NT2 * COLS2];
__device__ float g_Us1[L * 4];
__device__ float g_wy[NB * NWY * NC];
__device__ unsigned g_idx3[NT3];
__device__ unsigned g_idx2[NT2];

// ---------------- packed f32x2 helpers ----------------
__device__ __forceinline__ ull pack2(float v) {
    ull r;
    asm("mov.b64 %0, {%1, %1};" : "=l"(r) : "f"(v));
    return r;
}
__device__ __forceinline__ void unpack2(ull v, float& lo, float& hi) {
    asm("mov.b64 {%0, %1}, %2;" : "=f"(lo), "=f"(hi) : "l"(v));
}
__device__ __forceinline__ void fma2(ull& d, ull a, ull b) {
    asm("fma.rn.f32x2 %0, %1, %2, %0;" : "+l"(d) : "l"(a), "l"(b));
}

// ---------------- K0: symmetrization + index tables ----------------
__global__ void k_setup(const float* __restrict__ U1_0e, const float* __restrict__ U2_0e,
                        const float* __restrict__ U3_0e, const float* __restrict__ U1_1o,
                        const float* __restrict__ U2_1o, const float* __restrict__ U3_1o) {
    int blk = blockIdx.x;
    int j = threadIdx.x;
    if (blk < NT3) {
        int t = blk;
        int rem = t, A = 0, B = 0, D = 0;
        {
            int i = 0;
            for (;;) { int m = L - i; int cnt = m * (m + 1) / 2;
                       if (rem < cnt) break; rem -= cnt; i++; }
            A = i;
            int q = A;
            for (;;) { int cnt = L - q;
                       if (rem < cnt) break; rem -= cnt; q++; }
            B = q; D = B + rem;
        }
        if (j == 0) g_idx3[t] = (unsigned)A | ((unsigned)B << 8) | ((unsigned)D << 16);
        int P[6][3] = {{A,B,D},{A,D,B},{B,A,D},{B,D,A},{D,A,B},{D,B,A}};
        float val = 0.f;
        if (j < 122) {
            for (int i = 0; i < 6; i++) {
                bool dup = false;
                for (int q = 0; q < i; q++)
                    if (P[q][0] == P[i][0] && P[q][1] == P[i][1] && P[q][2] == P[i][2]) dup = true;
                if (dup) continue;
                int p0 = P[i][0], p1 = P[i][1], p2 = P[i][2];
                if (j < 23) {
                    val += U3_0e[((p0 * L + p1) * L + p2) * 23 + j];
                } else {
                    int w = (j - 23) / 33, k = (j - 23) % 33;
                    val += U3_1o[(((w * L + p0) * L + p1) * L + p2) * 33 + k];
                }
            }
        }
        g_Us3[t * COLS3 + j] = val;
    } else if (blk < NT3 + NT2) {
        int t = blk - NT3;
        int rem = t, A = 0, B = 0;
        {
            int i = 0;
            for (;;) { int cnt = L - i;
                       if (rem < cnt) break; rem -= cnt; i++; }
            A = i; B = A + rem;
        }
        if (j == 0) g_idx2[t] = (unsigned)A | ((unsigned)B << 8);
        if (j >= COLS2) return;
        float val = 0.f;
        if (j < 22) {
            if (j < 4) {
                val = U2_0e[(A * L + B) * 4 + j];
                if (A != B) val += U2_0e[(B * L + A) * 4 + j];
            } else {
                int w = (j - 4) / 6, k = (j - 4) % 6;
                val = U2_1o[((w * L + A) * L + B) * 6 + k];
                if (A != B) val += U2_1o[((w * L + B) * L + A) * 6 + k];
            }
        }
        g_Us2[t * COLS2 + j] = val;
    } else {
        if (j >= L * 4) return;
        int a = j >> 2, col = j & 3;
        g_Us1[a * 4 + col] = (col == 0) ? U1_0e[a] : U1_1o[(col - 1) * L + a];
    }
}

// ---------------- K1: wy + zero output ----------------
__global__ void k_wy(const float* __restrict__ y,
                     const float* __restrict__ w3_0e, const float* __restrict__ w3_1o,
                     const float* __restrict__ w2_0e, const float* __restrict__ w2_1o,
                     const float* __restrict__ w1_0e, const float* __restrict__ w1_1o,
                     float* __restrict__ out) {
    int b = blockIdx.x;
    __shared__ float ys[NE];
    if (threadIdx.x < NE) ys[threadIdx.x] = y[b * NE + threadIdx.x];
    for (int i = threadIdx.x; i < 512; i += blockDim.x) out[b * 512 + i] = 0.f;
    __syncthreads();
    for (int idx = threadIdx.x; idx < NWY * NC; idx += blockDim.x) {
        int jw = idx >> 7, c = idx & 127;
        const float* wsrc; int K, k;
        if (jw < 23)       { wsrc = w3_0e; K = 23; k = jw; }
        else if (jw < 56)  { wsrc = w3_1o; K = 33; k = jw - 23; }
        else if (jw < 60)  { wsrc = w2_0e; K = 4;  k = jw - 56; }
        else if (jw < 66)  { wsrc = w2_1o; K = 6;  k = jw - 60; }
        else if (jw == 66) { wsrc = w1_0e; K = 1;  k = 0; }
        else               { wsrc = w1_1o; K = 1;  k = 0; }
        float acc = 0.f;
#pragma unroll
        for (int e = 0; e < NE; e++)
            acc = fmaf(wsrc[(e * K + k) * NC + c], ys[e], acc);
        g_wy[(b * NWY + jw) * NC + c] = acc;
    }
}

// ---------------- K2: main kernel ----------------
// grid = 256 blocks: (atom b, column-half h). 128 threads = channels.
#define SLAB (CH * 64)
#define SM_FLOATS (2 * SLAB + NC * 17 + NT3 + NT2)

__device__ __forceinline__ void stage3(float* dst, int q, int h, int tid) {
    const float4* src = (const float4*)g_Us3;
    float4* d4 = (float4*)dst;
    for (int i = tid; i < CH * 16; i += NC) {
        int r = i >> 4, qq = i & 15;
        d4[i] = src[(q * CH + r) * (COLS3 / 4) + h * 16 + qq];
    }
}

__global__ void __launch_bounds__(128) k_main(const float* __restrict__ x,
                                              float* __restrict__ out) {
    extern __shared__ float sm[];
    float* slab0 = sm;
    float* slab1 = sm + SLAB;
    float* Xs    = sm + 2 * SLAB;
    unsigned* sIdx3 = (unsigned*)(Xs + NC * 17);
    unsigned* sIdx2 = sIdx3 + NT3;

    const int tid = threadIdx.x;          // channel
    const int b = blockIdx.x >> 1;
    const int h = blockIdx.x & 1;         // column half (64 cols)

    float* Xc = Xs + tid * 17;
    {
        const float4* xp = (const float4*)(x + (b * NC + tid) * L);
#pragma unroll
        for (int q = 0; q < 4; q++) {
            float4 v = xp[q];
            Xc[4 * q + 0] = v.x; Xc[4 * q + 1] = v.y;
            Xc[4 * q + 2] = v.z; Xc[4 * q + 3] = v.w;
        }
    }
    for (int i = tid; i < NT3; i += NC) sIdx3[i] = g_idx3[i];
    for (int i = tid; i < NT2; i += NC) sIdx2[i] = g_idx2[i];

    stage3(slab0, 0, h, tid);
    __syncthreads();

    ull acc[32];
#pragma unroll
    for (int w = 0; w < 32; w++) acc[w] = 0ull;

    // ===== order-3 main loop: 8 chunks of 102 triples =====
    for (int q = 0; q < NCHUNK; q++) {
        float* cur = (q & 1) ? slab1 : slab0;
        float* nxt = (q & 1) ? slab0 : slab1;
        if (q < NCHUNK - 1) stage3(nxt, q + 1, h, tid);

        const unsigned* it = sIdx3 + q * CH;
        const ulonglong2* rowp = (const ulonglong2*)cur;
#pragma unroll 2
        for (int tt = 0; tt < CH; tt++) {
            unsigned u = it[tt];
            float m = Xc[u & 255] * Xc[(u >> 8) & 255] * Xc[(u >> 16) & 255];
            ull m2 = pack2(m);
#pragma unroll
            for (int k = 0; k < 16; k++) {            // FIX: 16 ulonglong2 = full 64-float row
                ulonglong2 cvec = rowp[k];
                fma2(acc[2 * k],     m2, cvec.x);
                fma2(acc[2 * k + 1], m2, cvec.y);
            }
            rowp += 16;                               // FIX: advance full row (256 B)
        }
        __syncthreads();
    }

    // ===== order-3 epilogue =====
    float o0 = 0.f, o1 = 0.f, o2 = 0.f, o3 = 0.f;
    const float* wyb = g_wy + b * NWY * NC + tid;
#pragma unroll
    for (int w = 0; w < 32; w++) {
        float lo, hi;
        unpack2(acc[w], lo, hi);
#pragma unroll
        for (int hh = 0; hh < 2; hh++) {
            int j = h * 64 + 2 * w + hh;
            float v = (hh == 0) ? lo : hi;
            if (j < 122) {
                int tgt, wyc;
                if (j < 23) { tgt = 0; wyc = j; }
                else {
                    int wq = (j - 23) / 33;
                    tgt = 1 + wq;
                    wyc = 23 + (j - 23 - wq * 33);
                }
                float contrib = v * wyb[wyc * NC];
                if (tgt == 0) o0 += contrib;
                else if (tgt == 1) o1 += contrib;
                else if (tgt == 2) o2 += contrib;
                else o3 += contrib;
            }
        }
    }

    // ===== order-2: 12 cols per half =====
    {
        const float4* src = (const float4*)g_Us2;
        float4* d4 = (float4*)slab0;
        for (int i = tid; i < NT2 * 3; i += NC) {
            int r = i / 3, qq = i - r * 3;
            d4[i] = src[r * (COLS2 / 4) + h * 3 + qq];
        }
        __syncthreads();

        ull acc2[6];
#pragma unroll
        for (int w = 0; w < 6; w++) acc2[w] = 0ull;
        const ulonglong2* rp = (const ulonglong2*)slab0;
#pragma unroll 4
        for (int tt = 0; tt < NT2; tt++) {
            unsigned u = sIdx2[tt];
            ull m2 = pack2(Xc[u & 255] * Xc[(u >> 8) & 255]);
            ulonglong2 a0 = rp[0], a1 = rp[1], a2 = rp[2];
            fma2(acc2[0], m2, a0.x); fma2(acc2[1], m2, a0.y);
            fma2(acc2[2], m2, a1.x); fma2(acc2[3], m2, a1.y);
            fma2(acc2[4], m2, a2.x); fma2(acc2[5], m2, a2.y);
            rp += 3;
        }
#pragma unroll
        for (int w = 0; w < 6; w++) {
            float lo, hi;
            unpack2(acc2[w], lo, hi);
#pragma unroll
            for (int hh = 0; hh < 2; hh++) {
                int j = h * 12 + 2 * w + hh;
                float v = (hh == 0) ? lo : hi;
                if (j < 22) {
                    int tgt, wyc;
                    if (j < 4) { tgt = 0; wyc = 56 + j; }
                    else {
                        int wq = (j - 4) / 6;
                        tgt = 1 + wq;
                        wyc = 60 + (j - 4 - wq * 6);
                    }
                    float contrib = v * wyb[wyc * NC];
                    if (tgt == 0) o0 += contrib;
                    else if (tgt == 1) o1 += contrib;
                    else if (tgt == 2) o2 += contrib;
                    else o3 += contrib;
                }
            }
        }
    }

    // ===== order-1 (half 1 only) =====
    if (h == 1) {
        float P0 = 0.f, P1 = 0.f, P2 = 0.f, P3 = 0.f;
#pragma unroll
        for (int a = 0; a < L; a++) {
            float xa = Xc[a];
            P0 = fmaf(g_Us1[a * 4 + 0], xa, P0);
            P1 = fmaf(g_Us1[a * 4 + 1], xa, P1);
            P2 = fmaf(g_Us1[a * 4 + 2], xa, P2);
            P3 = fmaf(g_Us1[a * 4 + 3], xa, P3);
        }
        float wv66 = wyb[66 * NC], wv67 = wyb[67 * NC];
        o0 = fmaf(P0, wv66, o0);
        o1 = fmaf(P1, wv67, o1);
        o2 = fmaf(P2, wv67, o2);
        o3 = fmaf(P3, wv67, o3);
    }

    // ===== output: exactly 2 atomic adds per element (order-independent sum) =====
    float* ob = out + b * 512;
    atomicAdd(&ob[tid], o0);
    atomicAdd(&ob[128 + 3 * tid + 0], o1);
    atomicAdd(&ob[128 + 3 * tid + 1], o2);
    atomicAdd(&ob[128 + 3 * tid + 2], o3);
}

static const size_t SMEM_BYTES = (size_t)SM_FLOATS * sizeof(float);  // ~64.7 KB

extern "C" void kernel_launch(void* const* d_in, const int* in_sizes, int n_in,
                              void* d_out, int out_size) {
    const float* x      = (const float*)d_in[0];
    const float* y      = (const float*)d_in[1];
    const float* U1_0e  = (const float*)d_in[2];
    const float* U2_0e  = (const float*)d_in[3];
    const float* U3_0e  = (const float*)d_in[4];
    const float* U1_1o  = (const float*)d_in[5];
    const float* U2_1o  = (const float*)d_in[6];
    const float* U3_1o  = (const float*)d_in[7];
    const float* w1_0e  = (const float*)d_in[8];
    const float* w2_0e  = (const float*)d_in[9];
    const float* w3_0e  = (const float*)d_in[10];
    const float* w1_1o  = (const float*)d_in[11];
    const float* w2_1o  = (const float*)d_in[12];
    const float* w3_1o  = (const float*)d_in[13];
    float* out = (float*)d_out;

    cudaFuncSetAttribute(k_main, cudaFuncAttributeMaxDynamicSharedMemorySize,
                         (int)SMEM_BYTES);

    k_setup<<<NT3 + NT2 + 1, 128>>>(U1_0e, U2_0e, U3_0e, U1_1o, U2_1o, U3_1o);
    k_wy<<<NB, 256>>>(y, w3_0e, w3_1o, w2_0e, w2_1o, w1_0e, w1_1o, out);
    k_main<<<2 * NB, 128, SMEM_BYTES>>>(x, out);
}

// round 6
// speedup vs baseline: 1.2897x; 1.2752x over previous
#include <cuda_runtime.h>

#define L   16
#define NB  128
#define NC  128
#define NE  10
#define NT3 816
#define NT2 136
#define COLS3 128   // padded (122 real)
#define COLS2 24    // padded (22 real)
#define NWY 68
#define CH  51
#define NCHUNK 16   // 51*16 = 816

typedef unsigned long long ull;

__device__ float g_Us3[NT3 * COLS3];
__device__ float g_Us2[NT2 * COLS2];
__device__ float g_Us1[L * 4];
__device__ float g_wy[NB * NWY * NC];
__device__ unsigned g_idx3[NT3];
__device__ unsigned g_idx2[NT2];

// ---------------- packed f32x2 helpers ----------------
__device__ __forceinline__ ull pack2(float v) {
    ull r;
    asm("mov.b64 %0, {%1, %1};" : "=l"(r) : "f"(v));
    return r;
}
__device__ __forceinline__ void unpack2(ull v, float& lo, float& hi) {
    asm("mov.b64 {%0, %1}, %2;" : "=f"(lo), "=f"(hi) : "l"(v));
}
__device__ __forceinline__ void fma2(ull& d, ull a, ull b) {
    asm("fma.rn.f32x2 %0, %1, %2, %0;" : "+l"(d) : "l"(a), "l"(b));
}

// ---------------- K0: symmetrization + index tables ----------------
__global__ void k_setup(const float* __restrict__ U1_0e, const float* __restrict__ U2_0e,
                        const float* __restrict__ U3_0e, const float* __restrict__ U1_1o,
                        const float* __restrict__ U2_1o, const float* __restrict__ U3_1o) {
    int blk = blockIdx.x;
    int j = threadIdx.x;
    if (blk < NT3) {
        int t = blk;
        int rem = t, A = 0, B = 0, D = 0;
        {
            int i = 0;
            for (;;) { int m = L - i; int cnt = m * (m + 1) / 2;
                       if (rem < cnt) break; rem -= cnt; i++; }
            A = i;
            int q = A;
            for (;;) { int cnt = L - q;
                       if (rem < cnt) break; rem -= cnt; q++; }
            B = q; D = B + rem;
        }
        if (j == 0) g_idx3[t] = (unsigned)A | ((unsigned)B << 8) | ((unsigned)D << 16);
        int P[6][3] = {{A,B,D},{A,D,B},{B,A,D},{B,D,A},{D,A,B},{D,B,A}};
        float val = 0.f;
        if (j < 122) {
            for (int i = 0; i < 6; i++) {
                bool dup = false;
                for (int q = 0; q < i; q++)
                    if (P[q][0] == P[i][0] && P[q][1] == P[i][1] && P[q][2] == P[i][2]) dup = true;
                if (dup) continue;
                int p0 = P[i][0], p1 = P[i][1], p2 = P[i][2];
                if (j < 23) {
                    val += U3_0e[((p0 * L + p1) * L + p2) * 23 + j];
                } else {
                    int w = (j - 23) / 33, k = (j - 23) % 33;
                    val += U3_1o[(((w * L + p0) * L + p1) * L + p2) * 33 + k];
                }
            }
        }
        g_Us3[t * COLS3 + j] = val;
    } else if (blk < NT3 + NT2) {
        int t = blk - NT3;
        int rem = t, A = 0, B = 0;
        {
            int i = 0;
            for (;;) { int cnt = L - i;
                       if (rem < cnt) break; rem -= cnt; i++; }
            A = i; B = A + rem;
        }
        if (j == 0) g_idx2[t] = (unsigned)A | ((unsigned)B << 8);
        if (j >= COLS2) return;
        float val = 0.f;
        if (j < 22) {
            if (j < 4) {
                val = U2_0e[(A * L + B) * 4 + j];
                if (A != B) val += U2_0e[(B * L + A) * 4 + j];
            } else {
                int w = (j - 4) / 6, k = (j - 4) % 6;
                val = U2_1o[((w * L + A) * L + B) * 6 + k];
                if (A != B) val += U2_1o[((w * L + B) * L + A) * 6 + k];
            }
        }
        g_Us2[t * COLS2 + j] = val;
    } else {
        if (j >= L * 4) return;
        int a = j >> 2, col = j & 3;
        g_Us1[a * 4 + col] = (col == 0) ? U1_0e[a] : U1_1o[(col - 1) * L + a];
    }
}

// ---------------- K1: wy + order-1/2 contributions + output base ------------
// grid = NB blocks (one atom), 256 threads.
__global__ void __launch_bounds__(256) k_wy(
        const float* __restrict__ y, const float* __restrict__ x,
        const float* __restrict__ w3_0e, const float* __restrict__ w3_1o,
        const float* __restrict__ w2_0e, const float* __restrict__ w2_1o,
        const float* __restrict__ w1_0e, const float* __restrict__ w1_1o,
        float* __restrict__ out) {
    __shared__ __align__(16) float ys[NE];
    __shared__ __align__(16) float Xs[NC * 17];
    __shared__ __align__(16) float wys[12 * NC];       // wy rows 56..67
    __shared__ __align__(16) float Us2s[NT2 * COLS2];  // 13 KB
    __shared__ __align__(16) float Us1s[L * 4];
    __shared__ __align__(16) float red2[NC * 4 * 2];
    const int tid = threadIdx.x;
    const int b = blockIdx.x;

    if (tid < NE) ys[tid] = y[b * NE + tid];
    if (tid < L * 4) Us1s[tid] = g_Us1[tid];
    // load X[b] into padded smem
    {
        int c = tid >> 1, off = (tid & 1) * 8;
        const float4* xp = (const float4*)(x + (b * NC + c) * L + off);
        float4 v0 = xp[0], v1 = xp[1];
        float* dst = Xs + c * 17 + off;
        dst[0] = v0.x; dst[1] = v0.y; dst[2] = v0.z; dst[3] = v0.w;
        dst[4] = v1.x; dst[5] = v1.y; dst[6] = v1.z; dst[7] = v1.w;
    }
    // stage symmetrized order-2 table
    for (int i = tid; i < NT2 * (COLS2 / 4); i += 256)
        ((float4*)Us2s)[i] = ((const float4*)g_Us2)[i];
    __syncthreads();

    // wy[b][jw][c]
    for (int idx = tid; idx < NWY * NC; idx += 256) {
        int jw = idx >> 7, c = idx & 127;
        const float* wsrc; int K, k;
        if (jw < 23)       { wsrc = w3_0e; K = 23; k = jw; }
        else if (jw < 56)  { wsrc = w3_1o; K = 33; k = jw - 23; }
        else if (jw < 60)  { wsrc = w2_0e; K = 4;  k = jw - 56; }
        else if (jw < 66)  { wsrc = w2_1o; K = 6;  k = jw - 60; }
        else if (jw == 66) { wsrc = w1_0e; K = 1;  k = 0; }
        else               { wsrc = w1_1o; K = 1;  k = 0; }
        float acc = 0.f;
#pragma unroll
        for (int e = 0; e < NE; e++)
            acc = fmaf(wsrc[(e * K + k) * NC + c], ys[e], acc);
        g_wy[(b * NWY + jw) * NC + c] = acc;
        if (jw >= 56) wys[(jw - 56) * NC + c] = acc;
    }
    __syncthreads();

    // order-2: thread = (channel c, pair-half)
    const int c = tid & 127;
    const int half = tid >> 7;
    const float* Xc = Xs + c * 17;
    ull P2[11];
#pragma unroll
    for (int k = 0; k < 11; k++) P2[k] = 0ull;
    for (int t = half * 68; t < half * 68 + 68; t++) {
        unsigned u = g_idx2[t];
        ull m2 = pack2(Xc[u & 255] * Xc[(u >> 8) & 255]);
        const ull* row = (const ull*)(Us2s + t * COLS2);
#pragma unroll
        for (int k = 0; k < 11; k++) fma2(P2[k], m2, row[k]);
    }
    float contrib[4] = {0.f, 0.f, 0.f, 0.f};
#pragma unroll
    for (int k = 0; k < 11; k++) {
        float lo, hi;
        unpack2(P2[k], lo, hi);
#pragma unroll
        for (int hh = 0; hh < 2; hh++) {
            int j = 2 * k + hh;
            float v = (hh == 0) ? lo : hi;
            int tgt, row;
            if (j < 4) { tgt = 0; row = j; }             // wy 56+j
            else { int wq = (j - 4) / 6; tgt = 1 + wq; row = 4 + (j - 4 - wq * 6); }
            contrib[tgt] += v * wys[row * NC + c];
        }
    }
    if (half == 0) {   // order-1
        float P0 = 0.f, P1 = 0.f, Pq = 0.f, P3 = 0.f;
#pragma unroll
        for (int a = 0; a < L; a++) {
            float xa = Xc[a];
            P0 = fmaf(Us1s[a * 4 + 0], xa, P0);
            P1 = fmaf(Us1s[a * 4 + 1], xa, P1);
            Pq = fmaf(Us1s[a * 4 + 2], xa, Pq);
            P3 = fmaf(Us1s[a * 4 + 3], xa, P3);
        }
        contrib[0] = fmaf(P0, wys[10 * NC + c], contrib[0]);
        contrib[1] = fmaf(P1, wys[11 * NC + c], contrib[1]);
        contrib[2] = fmaf(Pq, wys[11 * NC + c], contrib[2]);
        contrib[3] = fmaf(P3, wys[11 * NC + c], contrib[3]);
    }
#pragma unroll
    for (int tgt = 0; tgt < 4; tgt++)
        red2[(c * 4 + tgt) * 2 + half] = contrib[tgt];
    __syncthreads();
    for (int i = tid; i < 512; i += 256) {
        int cc = i >> 2, tgt = i & 3;
        float v = red2[i * 2] + red2[i * 2 + 1];
        if (tgt == 0) out[b * 512 + cc] = v;
        else out[b * 512 + 128 + 3 * cc + (tgt - 1)] = v;
    }
}

// ---------------- K2: order-3 GEMM-style register-blocked kernel ------------
// grid = 256 blocks: (atom b, col-half h). 256 threads: (chg 0..31, colg 0..7).
// Thread tile: 4 channels (c0=4*chg) x 8 columns (j0=8*colg).
// smem floats: Msm[51*128] | Cd[51*64] | Xs[128*17] | sIdx[816 uint]
#define MSM_F (CH * NC)                   // 6528
#define CD_F  (CH * 64)                   // 3264
#define XS_F  (NC * 17)                   // 2176
#define SM_FLOATS (MSM_F + CD_F + XS_F + NT3)

__global__ void __launch_bounds__(256) k_main(const float* __restrict__ x,
                                              float* __restrict__ out) {
    extern __shared__ float sm[];
    float* Msm = sm;
    float* Cd  = sm + MSM_F;
    float* Xs  = sm + MSM_F + CD_F;
    unsigned* sIdx = (unsigned*)(sm + MSM_F + CD_F + XS_F);

    const int tid = threadIdx.x;
    const int b = blockIdx.x >> 1;
    const int h = blockIdx.x & 1;
    const int c0 = (tid & 31) * 4;
    const int j0 = (tid >> 5) * 8;

    // load X[b] into padded smem
    {
        int c = tid >> 1, off = (tid & 1) * 8;
        const float4* xp = (const float4*)(x + (b * NC + c) * L + off);
        float4 v0 = xp[0], v1 = xp[1];
        float* dst = Xs + c * 17 + off;
        dst[0] = v0.x; dst[1] = v0.y; dst[2] = v0.z; dst[3] = v0.w;
        dst[4] = v1.x; dst[5] = v1.y; dst[6] = v1.z; dst[7] = v1.w;
    }
    for (int i = tid; i < NT3; i += 256) sIdx[i] = g_idx3[i];
    __syncthreads();

    ull acc[16];
#pragma unroll
    for (int k = 0; k < 16; k++) acc[k] = 0ull;

    for (int q = 0; q < NCHUNK; q++) {
        // stage coefficient chunk: [51][64] from g_Us3[q*51+t][h*64+..]
        for (int i = tid; i < CH * 16; i += 256) {
            int t = i >> 4, f = i & 15;
            ((float4*)Cd)[t * 16 + f] =
                ((const float4*)(g_Us3 + (q * CH + t) * COLS3 + h * 64))[f];
        }
        // build monomial chunk: [51][128]
        for (int i = tid; i < CH * NC; i += 256) {
            int t = i >> 7, c = i & 127;
            unsigned u = sIdx[q * CH + t];
            const float* Xc = Xs + c * 17;
            Msm[i] = Xc[u & 255] * Xc[(u >> 8) & 255] * Xc[(u >> 16) & 255];
        }
        __syncthreads();

        const ulonglong2* mp = (const ulonglong2*)Msm + (c0 >> 2);
        const float4* cp = (const float4*)Cd + (j0 >> 2);
#pragma unroll 3
        for (int t = 0; t < CH; t++) {
            ulonglong2 mv = mp[t * 32];                  // m[c0..c0+3]
            float4 ca = cp[t * 16], cb = cp[t * 16 + 1]; // C[t][j0..j0+7]
            ull d0 = pack2(ca.x), d1 = pack2(ca.y), d2 = pack2(ca.z), d3 = pack2(ca.w);
            ull d4 = pack2(cb.x), d5 = pack2(cb.y), d6 = pack2(cb.z), d7 = pack2(cb.w);
            fma2(acc[0], mv.x, d0);  fma2(acc[1], mv.x, d1);
            fma2(acc[2], mv.x, d2);  fma2(acc[3], mv.x, d3);
            fma2(acc[4], mv.x, d4);  fma2(acc[5], mv.x, d5);
            fma2(acc[6], mv.x, d6);  fma2(acc[7], mv.x, d7);
            fma2(acc[8],  mv.y, d0); fma2(acc[9],  mv.y, d1);
            fma2(acc[10], mv.y, d2); fma2(acc[11], mv.y, d3);
            fma2(acc[12], mv.y, d4); fma2(acc[13], mv.y, d5);
            fma2(acc[14], mv.y, d6); fma2(acc[15], mv.y, d7);
        }
        __syncthreads();
    }

    // epilogue: weight by wy, route to 4 targets
    float contrib[4][4];
#pragma unroll
    for (int a = 0; a < 4; a++)
#pragma unroll
        for (int t = 0; t < 4; t++) contrib[a][t] = 0.f;
    const float* wyb = g_wy + b * NWY * NC;
#pragma unroll
    for (int p = 0; p < 2; p++) {
#pragma unroll
        for (int j = 0; j < 8; j++) {
            float lo, hi;
            unpack2(acc[p * 8 + j], lo, hi);
            int jj = h * 64 + j0 + j;
            if (jj < 122) {
                int tgt, wyc;
                if (jj < 23) { tgt = 0; wyc = jj; }
                else { int wq = (jj - 23) / 33; tgt = 1 + wq; wyc = 23 + (jj - 23 - wq * 33); }
                int cA = c0 + 2 * p;
                contrib[2 * p][tgt]     += lo * wyb[wyc * NC + cA];
                contrib[2 * p + 1][tgt] += hi * wyb[wyc * NC + cA + 1];
            }
        }
    }

    // reduce over the 8 col-groups (reuse Msm region)
    float* red = Msm;   // [c][tgt][colg] : 512*8 floats
    const int colg = tid >> 5;
#pragma unroll
    for (int ch = 0; ch < 4; ch++)
#pragma unroll
        for (int tgt = 0; tgt < 4; tgt++)
            red[((c0 + ch) * 4 + tgt) * 8 + colg] = contrib[ch][tgt];
    __syncthreads();
    for (int i = tid; i < 512; i += 256) {
        const float* r = red + i * 8;
        float v = ((r[0] + r[1]) + (r[2] + r[3])) + ((r[4] + r[5]) + (r[6] + r[7]));
        int c = i >> 2, tgt = i & 3;
        if (tgt == 0) atomicAdd(&out[b * 512 + c], v);
        else atomicAdd(&out[b * 512 + 128 + 3 * c + (tgt - 1)], v);
    }
}

static const size_t SMEM_BYTES = (size_t)SM_FLOATS * sizeof(float);  // 51,136 B

extern "C" void kernel_launch(void* const* d_in, const int* in_sizes, int n_in,
                              void* d_out, int out_size) {
    const float* x      = (const float*)d_in[0];
    const float* y      = (const float*)d_in[1];
    const float* U1_0e  = (const float*)d_in[2];
    const float* U2_0e  = (const float*)d_in[3];
    const float* U3_0e  = (const float*)d_in[4];
    const float* U1_1o  = (const float*)d_in[5];
    const float* U2_1o  = (const float*)d_in[6];
    const float* U3_1o  = (const float*)d_in[7];
    const float* w1_0e  = (const float*)d_in[8];
    const float* w2_0e  = (const float*)d_in[9];
    const float* w3_0e  = (const float*)d_in[10];
    const float* w1_1o  = (const float*)d_in[11];
    const float* w2_1o  = (const float*)d_in[12];
    const float* w3_1o  = (const float*)d_in[13];
    float* out = (float*)d_out;

    cudaFuncSetAttribute(k_main, cudaFuncAttributeMaxDynamicSharedMemorySize,
                         (int)SMEM_BYTES);

    k_setup<<<NT3 + NT2 + 1, 128>>>(U1_0e, U2_0e, U3_0e, U1_1o, U2_1o, U3_1o);
    k_wy<<<NB, 256>>>(y, x, w3_0e, w3_1o, w2_0e, w2_1o, w1_0e, w1_1o, out);
    k_main<<<2 * NB, 256, SMEM_BYTES>>>(x, out);
}

// round 8
// speedup vs baseline: 1.8018x; 1.3971x over previous
#include <cuda_runtime.h>
#include <cuda_bf16.h>
#include <cstdint>

#define L    16
#define NB   128
#define NC   128
#define NE   10
#define NT3  816
#define NT3P 832      // padded to 13*64
#define NT2  136
#define COLS2 24
#define NWY  68
#define NCHUNK 13     // K chunks of 64

typedef unsigned long long ull;

// ---------------- device globals ----------------
__device__ unsigned g_idx3[NT3];
__device__ unsigned g_idx2[NT2];
__device__ float    g_Us2[NT2 * COLS2];
__device__ float    g_Us1[L * 4];
__device__ float    g_wy[NB * NWY * NC];
// split-bf16 coefficient chunk images, row-major: [chunk][j=128][t_in=64]
__device__ __align__(16) __nv_bfloat16 g_B3hi[NCHUNK * 8192];
__device__ __align__(16) __nv_bfloat16 g_B3lo[NCHUNK * 8192];

// ---------------- helpers ----------------
__device__ __forceinline__ uint32_t smem_u32(const void* p) {
    uint32_t a;
    asm("{ .reg .u64 t; cvta.to.shared.u64 t, %1; cvt.u32.u64 %0, t; }" : "=r"(a) : "l"(p));
    return a;
}
__device__ __forceinline__ ull pack2(float v) {
    ull r; asm("mov.b64 %0, {%1, %1};" : "=l"(r) : "f"(v)); return r;
}
__device__ __forceinline__ void unpack2(ull v, float& lo, float& hi) {
    asm("mov.b64 {%0, %1}, %2;" : "=f"(lo), "=f"(hi) : "l"(v));
}
__device__ __forceinline__ void fma2(ull& d, ull a, ull b) {
    asm("fma.rn.f32x2 %0, %1, %2, %0;" : "+l"(d) : "l"(a), "l"(b));
}
// pack two f32 -> bf16x2 (low half = a, high half = b)
__device__ __forceinline__ uint32_t cvt_bf16x2(float a, float b) {
    uint32_t r;
    asm("cvt.rn.satfinite.bf16x2.f32 %0, %1, %2;" : "=r"(r) : "f"(b), "f"(a));
    return r;
}
__device__ __forceinline__ void ldsm4(uint32_t* r, uint32_t addr) {
    asm volatile("ldmatrix.sync.aligned.m8n8.x4.shared.b16 {%0,%1,%2,%3}, [%4];"
                 : "=r"(r[0]), "=r"(r[1]), "=r"(r[2]), "=r"(r[3]) : "r"(addr));
}
__device__ __forceinline__ void mma16816(float* d, const uint32_t* a,
                                         uint32_t b0, uint32_t b1) {
    asm volatile("mma.sync.aligned.m16n8k16.row.col.f32.bf16.bf16.f32 "
                 "{%0,%1,%2,%3}, {%4,%5,%6,%7}, {%8,%9}, {%0,%1,%2,%3};"
                 : "+f"(d[0]), "+f"(d[1]), "+f"(d[2]), "+f"(d[3])
                 : "r"(a[0]), "r"(a[1]), "r"(a[2]), "r"(a[3]), "r"(b0), "r"(b1));
}

// ---------------- K0: symmetrize + bf16-split ----------------
// blocks [0,832): triple t (>=816 -> zeros); [832,968): pair; 968: order-1.
__global__ void k_setup(const float* __restrict__ U1_0e, const float* __restrict__ U2_0e,
                        const float* __restrict__ U3_0e, const float* __restrict__ U1_1o,
                        const float* __restrict__ U2_1o, const float* __restrict__ U3_1o) {
    int blk = blockIdx.x;
    int j = threadIdx.x;
    if (blk < NT3P) {
        int t = blk;
        float val = 0.f;
        if (t < NT3) {
            int rem = t, A = 0, B = 0, D = 0;
            {
                int i = 0;
                for (;;) { int m = L - i; int cnt = m * (m + 1) / 2;
                           if (rem < cnt) break; rem -= cnt; i++; }
                A = i;
                int q = A;
                for (;;) { int cnt = L - q;
                           if (rem < cnt) break; rem -= cnt; q++; }
                B = q; D = B + rem;
            }
            if (j == 0) g_idx3[t] = (unsigned)A | ((unsigned)B << 8) | ((unsigned)D << 16);
            int P[6][3] = {{A,B,D},{A,D,B},{B,A,D},{B,D,A},{D,A,B},{D,B,A}};
            if (j < 122) {
                for (int i = 0; i < 6; i++) {
                    bool dup = false;
                    for (int q = 0; q < i; q++)
                        if (P[q][0] == P[i][0] && P[q][1] == P[i][1] && P[q][2] == P[i][2]) dup = true;
                    if (dup) continue;
                    int p0 = P[i][0], p1 = P[i][1], p2 = P[i][2];
                    if (j < 23) {
                        val += U3_0e[((p0 * L + p1) * L + p2) * 23 + j];
                    } else {
                        int w = (j - 23) / 33, k = (j - 23) % 33;
                        val += U3_1o[(((w * L + p0) * L + p1) * L + p2) * 33 + k];
                    }
                }
            }
        }
        __nv_bfloat16 hv = __float2bfloat16(val);
        float hf = __bfloat162float(hv);
        __nv_bfloat16 lv = __float2bfloat16(val - hf);
        int chunk = t >> 6, t_in = t & 63;
        // row-major chunk image: [j][t_in]
        g_B3hi[chunk * 8192 + j * 64 + t_in] = hv;
        g_B3lo[chunk * 8192 + j * 64 + t_in] = lv;
    } else if (blk < NT3P + NT2) {
        int t = blk - NT3P;
        int rem = t, A = 0, B = 0;
        {
            int i = 0;
            for (;;) { int cnt = L - i;
                       if (rem < cnt) break; rem -= cnt; i++; }
            A = i; B = A + rem;
        }
        if (j == 0) g_idx2[t] = (unsigned)A | ((unsigned)B << 8);
        if (j >= COLS2) return;
        float val = 0.f;
        if (j < 22) {
            if (j < 4) {
                val = U2_0e[(A * L + B) * 4 + j];
                if (A != B) val += U2_0e[(B * L + A) * 4 + j];
            } else {
                int w = (j - 4) / 6, k = (j - 4) % 6;
                val = U2_1o[((w * L + A) * L + B) * 6 + k];
                if (A != B) val += U2_1o[((w * L + B) * L + A) * 6 + k];
            }
        }
        g_Us2[t * COLS2 + j] = val;
    } else {
        if (j >= L * 4) return;
        int a = j >> 2, col = j & 3;
        g_Us1[a * 4 + col] = (col == 0) ? U1_0e[a] : U1_1o[(col - 1) * L + a];
    }
}

// ---------------- K1: wy + order-1/2 + output base (passing since R6) ------
__global__ void __launch_bounds__(256) k_wy(
        const float* __restrict__ y, const float* __restrict__ x,
        const float* __restrict__ w3_0e, const float* __restrict__ w3_1o,
        const float* __restrict__ w2_0e, const float* __restrict__ w2_1o,
        const float* __restrict__ w1_0e, const float* __restrict__ w1_1o,
        float* __restrict__ out) {
    __shared__ __align__(16) float ys[NE];
    __shared__ __align__(16) float Xs[NC * 17];
    __shared__ __align__(16) float wys[12 * NC];
    __shared__ __align__(16) float Us2s[NT2 * COLS2];
    __shared__ __align__(16) float Us1s[L * 4];
    __shared__ __align__(16) float red2[NC * 4 * 2];
    const int tid = threadIdx.x;
    const int b = blockIdx.x;

    if (tid < NE) ys[tid] = y[b * NE + tid];
    if (tid < L * 4) Us1s[tid] = g_Us1[tid];
    {
        int c = tid >> 1, off = (tid & 1) * 8;
        const float4* xp = (const float4*)(x + (b * NC + c) * L + off);
        float4 v0 = xp[0], v1 = xp[1];
        float* dst = Xs + c * 17 + off;
        dst[0] = v0.x; dst[1] = v0.y; dst[2] = v0.z; dst[3] = v0.w;
        dst[4] = v1.x; dst[5] = v1.y; dst[6] = v1.z; dst[7] = v1.w;
    }
    for (int i = tid; i < NT2 * (COLS2 / 4); i += 256)
        ((float4*)Us2s)[i] = ((const float4*)g_Us2)[i];
    __syncthreads();

    for (int idx = tid; idx < NWY * NC; idx += 256) {
        int jw = idx >> 7, c = idx & 127;
        const float* wsrc; int K, k;
        if (jw < 23)       { wsrc = w3_0e; K = 23; k = jw; }
        else if (jw < 56)  { wsrc = w3_1o; K = 33; k = jw - 23; }
        else if (jw < 60)  { wsrc = w2_0e; K = 4;  k = jw - 56; }
        else if (jw < 66)  { wsrc = w2_1o; K = 6;  k = jw - 60; }
        else if (jw == 66) { wsrc = w1_0e; K = 1;  k = 0; }
        else               { wsrc = w1_1o; K = 1;  k = 0; }
        float acc = 0.f;
#pragma unroll
        for (int e = 0; e < NE; e++)
            acc = fmaf(wsrc[(e * K + k) * NC + c], ys[e], acc);
        g_wy[(b * NWY + jw) * NC + c] = acc;
        if (jw >= 56) wys[(jw - 56) * NC + c] = acc;
    }
    __syncthreads();

    const int c = tid & 127;
    const int half = tid >> 7;
    const float* Xc = Xs + c * 17;
    ull P2[11];
#pragma unroll
    for (int k = 0; k < 11; k++) P2[k] = 0ull;
    for (int t = half * 68; t < half * 68 + 68; t++) {
        unsigned u = g_idx2[t];
        ull m2 = pack2(Xc[u & 255] * Xc[(u >> 8) & 255]);
        const ull* row = (const ull*)(Us2s + t * COLS2);
#pragma unroll
        for (int k = 0; k < 11; k++) fma2(P2[k], m2, row[k]);
    }
    float contrib[4] = {0.f, 0.f, 0.f, 0.f};
#pragma unroll
    for (int k = 0; k < 11; k++) {
        float lo, hi;
        unpack2(P2[k], lo, hi);
#pragma unroll
        for (int hh = 0; hh < 2; hh++) {
            int j = 2 * k + hh;
            float v = (hh == 0) ? lo : hi;
            int tgt, row;
            if (j < 4) { tgt = 0; row = j; }
            else { int wq = (j - 4) / 6; tgt = 1 + wq; row = 4 + (j - 4 - wq * 6); }
            contrib[tgt] += v * wys[row * NC + c];
        }
    }
    if (half == 0) {
        float P0 = 0.f, P1 = 0.f, Pq = 0.f, P3 = 0.f;
#pragma unroll
        for (int a = 0; a < L; a++) {
            float xa = Xc[a];
            P0 = fmaf(Us1s[a * 4 + 0], xa, P0);
            P1 = fmaf(Us1s[a * 4 + 1], xa, P1);
            Pq = fmaf(Us1s[a * 4 + 2], xa, Pq);
            P3 = fmaf(Us1s[a * 4 + 3], xa, P3);
        }
        contrib[0] = fmaf(P0, wys[10 * NC + c], contrib[0]);
        contrib[1] = fmaf(P1, wys[11 * NC + c], contrib[1]);
        contrib[2] = fmaf(Pq, wys[11 * NC + c], contrib[2]);
        contrib[3] = fmaf(P3, wys[11 * NC + c], contrib[3]);
    }
#pragma unroll
    for (int tgt = 0; tgt < 4; tgt++)
        red2[(c * 4 + tgt) * 2 + half] = contrib[tgt];
    __syncthreads();
    for (int i = tid; i < 512; i += 256) {
        int cc = i >> 2, tgt = i & 3;
        float v = red2[i * 2] + red2[i * 2 + 1];
        if (tgt == 0) out[b * 512 + cc] = v;
        else out[b * 512 + 128 + 3 * cc + (tgt - 1)] = v;
    }
}

// ---------------- K2: order-3 via mma.sync (HMMA) ----------------
// grid = 128 (one atom/block); 256 threads = 8 warps; warp owns 16 rows.
// smem: Ah 16K | Al 16K | Bh 16K | Bl 16K | wys3 28K | Xs 8.5K | idx 3.3K
#define OFF_AH   0
#define OFF_AL   16384
#define OFF_BH   32768
#define OFF_BL   49152
#define OFF_WYS  65536
#define OFF_XS   94208
#define OFF_IDX  102912
#define SMEM_TOTAL 106176

__global__ void __launch_bounds__(256, 1) k_main(const float* __restrict__ x,
                                                 float* __restrict__ out) {
    extern __shared__ __align__(1024) char smc[];
    const uint32_t sb = smem_u32(smc);
    const int tid = threadIdx.x;
    const int wid = tid >> 5;
    const int lane = tid & 31;
    const int b = blockIdx.x;

    float* Xs = (float*)(smc + OFF_XS);
    float* wys3 = (float*)(smc + OFF_WYS);
    unsigned* sIdx = (unsigned*)(smc + OFF_IDX);

    // stage X (padded), wy rows 0..55, idx table
    {
        int c = tid >> 1, off = (tid & 1) * 8;
        const float4* xp = (const float4*)(x + (b * NC + c) * L + off);
        float4 v0 = xp[0], v1 = xp[1];
        float* dst = Xs + c * 17 + off;
        dst[0] = v0.x; dst[1] = v0.y; dst[2] = v0.z; dst[3] = v0.w;
        dst[4] = v1.x; dst[5] = v1.y; dst[6] = v1.z; dst[7] = v1.w;
    }
    {
        const float4* src = (const float4*)(g_wy + b * NWY * NC);
        float4* dst = (float4*)wys3;
        for (int i = tid; i < 56 * NC / 4; i += 256) dst[i] = src[i];
    }
    for (int i = tid; i < NT3; i += 256) sIdx[i] = g_idx3[i];
    __syncthreads();

    float acc[16][4];
#pragma unroll
    for (int nt = 0; nt < 16; nt++)
#pragma unroll
        for (int k = 0; k < 4; k++) acc[nt][k] = 0.f;

    const int r0 = wid * 16;
    const int mat = lane >> 3, lr = lane & 7;

    for (int q = 0; q < NCHUNK; q++) {
        // stage B chunk (row-major global -> XOR-swizzled smem)
        {
            const uint4* sh = (const uint4*)g_B3hi + q * 1024;
            const uint4* sl = (const uint4*)g_B3lo + q * 1024;
            for (int i = tid; i < 1024; i += 256) {
                int row = i >> 3, u = i & 7;
                uint32_t doff = (uint32_t)(row * 128 + ((u ^ (row & 7)) << 4));
                *(uint4*)(smc + OFF_BH + doff) = sh[i];
                *(uint4*)(smc + OFF_BL + doff) = sl[i];
            }
        }
        // build A chunk: monomials, bf16 split, XOR-swizzled store
        for (int item = tid; item < 1024; item += 256) {
            int c = item & 127, u = item >> 7;     // unit u -> 8 t's
            const float* Xc = Xs + c * 17;
            float m[8];
#pragma unroll
            for (int e = 0; e < 8; e++) {
                int gt = q * 64 + u * 8 + e;
                if (gt < NT3) {
                    unsigned uu = sIdx[gt];
                    m[e] = Xc[uu & 255] * Xc[(uu >> 8) & 255] * Xc[(uu >> 16) & 255];
                } else m[e] = 0.f;
            }
            uint32_t hi[4], lo[4];
#pragma unroll
            for (int p = 0; p < 4; p++) {
                uint32_t hp = cvt_bf16x2(m[2 * p], m[2 * p + 1]);
                float h0 = __uint_as_float(hp << 16);
                float h1 = __uint_as_float(hp & 0xffff0000u);
                lo[p] = cvt_bf16x2(m[2 * p] - h0, m[2 * p + 1] - h1);
                hi[p] = hp;
            }
            uint32_t doff = (uint32_t)(c * 128 + ((u ^ (c & 7)) << 4));
            *(uint4*)(smc + OFF_AH + doff) = make_uint4(hi[0], hi[1], hi[2], hi[3]);
            *(uint4*)(smc + OFF_AL + doff) = make_uint4(lo[0], lo[1], lo[2], lo[3]);
        }
        __syncthreads();

        // compute: 4 k-steps x 8 B-pairs x (hi*hi + hi*lo + lo*hi)
#pragma unroll
        for (int s = 0; s < 4; s++) {
            const int u0 = s * 2;
            // A fragments: matrices {rows0-7,k0-7},{rows8-15,k0-7},{rows0-7,k8-15},{rows8-15,k8-15}
            int arow = r0 + lr + (mat & 1) * 8;
            int au = u0 + (mat >> 1);
            uint32_t aoff = (uint32_t)(arow * 128 + ((au ^ (arow & 7)) << 4));
            uint32_t ah[4], al[4];
            ldsm4(ah, sb + OFF_AH + aoff);
            ldsm4(al, sb + OFF_AL + aoff);
#pragma unroll
            for (int p = 0; p < 8; p++) {
                // B matrices: {j0-7,k0-7},{j0-7,k8-15},{j8-15,k0-7},{j8-15,k8-15}
                int brow = p * 16 + (mat >> 1) * 8 + lr;
                int bu = u0 + (mat & 1);
                uint32_t boff = (uint32_t)(brow * 128 + ((bu ^ (brow & 7)) << 4));
                uint32_t bh[4], bl[4];
                ldsm4(bh, sb + OFF_BH + boff);
                ldsm4(bl, sb + OFF_BL + boff);
                mma16816(acc[2 * p],     ah, bh[0], bh[1]);
                mma16816(acc[2 * p],     ah, bl[0], bl[1]);
                mma16816(acc[2 * p],     al, bh[0], bh[1]);
                mma16816(acc[2 * p + 1], ah, bh[2], bh[3]);
                mma16816(acc[2 * p + 1], ah, bl[2], bl[3]);
                mma16816(acc[2 * p + 1], al, bh[2], bh[3]);
            }
        }
        __syncthreads();   // buffers reused next chunk
    }

    // ===== epilogue: weight by wy, quad-reduce, add to out =====
    const int r1 = r0 + (lane >> 2);           // row for c0/c1 (c2/c3 -> r1+8)
    float ct0[4] = {0.f, 0.f, 0.f, 0.f};       // row r1
    float ct1[4] = {0.f, 0.f, 0.f, 0.f};       // row r1+8
#pragma unroll
    for (int nt = 0; nt < 16; nt++) {
#pragma unroll
        for (int hh = 0; hh < 2; hh++) {
            int j = nt * 8 + 2 * (lane & 3) + hh;
            if (j < 122) {
                int tgt, wyc;
                if (j < 23) { tgt = 0; wyc = j; }
                else { int wq = (j - 23) / 33; tgt = 1 + wq; wyc = 23 + (j - 23 - wq * 33); }
                ct0[tgt] += acc[nt][hh]     * wys3[wyc * NC + r1];
                ct1[tgt] += acc[nt][2 + hh] * wys3[wyc * NC + r1 + 8];
            }
        }
    }
#pragma unroll
    for (int t = 0; t < 4; t++) {
        ct0[t] += __shfl_xor_sync(0xffffffffu, ct0[t], 1);
        ct0[t] += __shfl_xor_sync(0xffffffffu, ct0[t], 2);
        ct1[t] += __shfl_xor_sync(0xffffffffu, ct1[t], 1);
        ct1[t] += __shfl_xor_sync(0xffffffffu, ct1[t], 2);
    }
    if ((lane & 3) == 0) {
        float* ob = out + b * 512;
        int ra = r1, rb = r1 + 8;
        ob[ra] += ct0[0];
        ob[128 + 3 * ra + 0] += ct0[1];
        ob[128 + 3 * ra + 1] += ct0[2];
        ob[128 + 3 * ra + 2] += ct0[3];
        ob[rb] += ct1[0];
        ob[128 + 3 * rb + 0] += ct1[1];
        ob[128 + 3 * rb + 1] += ct1[2];
        ob[128 + 3 * rb + 2] += ct1[3];
    }
}

extern "C" void kernel_launch(void* const* d_in, const int* in_sizes, int n_in,
                              void* d_out, int out_size) {
    const float* x      = (const float*)d_in[0];
    const float* y      = (const float*)d_in[1];
    const float* U1_0e  = (const float*)d_in[2];
    const float* U2_0e  = (const float*)d_in[3];
    const float* U3_0e  = (const float*)d_in[4];
    const float* U1_1o  = (const float*)d_in[5];
    const float* U2_1o  = (const float*)d_in[6];
    const float* U3_1o  = (const float*)d_in[7];
    const float* w1_0e  = (const float*)d_in[8];
    const float* w2_0e  = (const float*)d_in[9];
    const float* w3_0e  = (const float*)d_in[10];
    const float* w1_1o  = (const float*)d_in[11];
    const float* w2_1o  = (const float*)d_in[12];
    const float* w3_1o  = (const float*)d_in[13];
    float* out = (float*)d_out;

    cudaFuncSetAttribute(k_main, cudaFuncAttributeMaxDynamicSharedMemorySize, SMEM_TOTAL);

    k_setup<<<NT3P + NT2 + 1, 128>>>(U1_0e, U2_0e, U3_0e, U1_1o, U2_1o, U3_1o);
    k_wy<<<NB, 256>>>(y, x, w3_0e, w3_1o, w2_0e, w2_1o, w1_0e, w1_1o, out);
    k_main<<<NB, 256, SMEM_TOTAL>>>(x, out);
}

// round 9
// speedup vs baseline: 2.2378x; 1.2420x over previous
#include <cuda_runtime.h>
#include <cuda_bf16.h>
#include <cstdint>

#define L    16
#define NB   128
#define NC   128
#define NE   10
#define NT3  816
#define NT3P 832      // padded to 13*64
#define NT2  136
#define COLS2 24
#define NWY  68
#define NCHUNK 13     // K chunks of 64

typedef unsigned long long ull;

// ---------------- device globals ----------------
__device__ unsigned g_idx3[NT3];
__device__ unsigned g_idx2[NT2];
__device__ float    g_Us2[NT2 * COLS2];
__device__ float    g_Us1[L * 4];
__device__ float    g_wy[NB * NWY * NC];
// split-bf16 coefficient chunk images, row-major: [chunk][j=128][t_in=64]
__device__ __align__(16) __nv_bfloat16 g_B3hi[NCHUNK * 8192];
__device__ __align__(16) __nv_bfloat16 g_B3lo[NCHUNK * 8192];

// ---------------- helpers ----------------
__device__ __forceinline__ uint32_t smem_u32(const void* p) {
    uint32_t a;
    asm("{ .reg .u64 t; cvta.to.shared.u64 t, %1; cvt.u32.u64 %0, t; }" : "=r"(a) : "l"(p));
    return a;
}
__device__ __forceinline__ ull pack2(float v) {
    ull r; asm("mov.b64 %0, {%1, %1};" : "=l"(r) : "f"(v)); return r;
}
__device__ __forceinline__ void unpack2(ull v, float& lo, float& hi) {
    asm("mov.b64 {%0, %1}, %2;" : "=f"(lo), "=f"(hi) : "l"(v));
}
__device__ __forceinline__ void fma2(ull& d, ull a, ull b) {
    asm("fma.rn.f32x2 %0, %1, %2, %0;" : "+l"(d) : "l"(a), "l"(b));
}
// pack two f32 -> bf16x2 (low half = a, high half = b)
__device__ __forceinline__ uint32_t cvt_bf16x2(float a, float b) {
    uint32_t r;
    asm("cvt.rn.satfinite.bf16x2.f32 %0, %1, %2;" : "=r"(r) : "f"(b), "f"(a));
    return r;
}
__device__ __forceinline__ void ldsm4(uint32_t* r, uint32_t addr) {
    asm volatile("ldmatrix.sync.aligned.m8n8.x4.shared.b16 {%0,%1,%2,%3}, [%4];"
                 : "=r"(r[0]), "=r"(r[1]), "=r"(r[2]), "=r"(r[3]) : "r"(addr));
}
__device__ __forceinline__ void mma16816(float* d, const uint32_t* a,
                                         uint32_t b0, uint32_t b1) {
    asm volatile("mma.sync.aligned.m16n8k16.row.col.f32.bf16.bf16.f32 "
                 "{%0,%1,%2,%3}, {%4,%5,%6,%7}, {%8,%9}, {%0,%1,%2,%3};"
                 : "+f"(d[0]), "+f"(d[1]), "+f"(d[2]), "+f"(d[3])
                 : "r"(a[0]), "r"(a[1]), "r"(a[2]), "r"(a[3]), "r"(b0), "r"(b1));
}

// ---------------- K0: symmetrize + bf16-split (unchanged, passing) ---------
__global__ void k_setup(const float* __restrict__ U1_0e, const float* __restrict__ U2_0e,
                        const float* __restrict__ U3_0e, const float* __restrict__ U1_1o,
                        const float* __restrict__ U2_1o, const float* __restrict__ U3_1o) {
    int blk = blockIdx.x;
    int j = threadIdx.x;
    if (blk < NT3P) {
        int t = blk;
        float val = 0.f;
        if (t < NT3) {
            int rem = t, A = 0, B = 0, D = 0;
            {
                int i = 0;
                for (;;) { int m = L - i; int cnt = m * (m + 1) / 2;
                           if (rem < cnt) break; rem -= cnt; i++; }
                A = i;
                int q = A;
                for (;;) { int cnt = L - q;
                           if (rem < cnt) break; rem -= cnt; q++; }
                B = q; D = B + rem;
            }
            if (j == 0) g_idx3[t] = (unsigned)A | ((unsigned)B << 8) | ((unsigned)D << 16);
            int P[6][3] = {{A,B,D},{A,D,B},{B,A,D},{B,D,A},{D,A,B},{D,B,A}};
            if (j < 122) {
                for (int i = 0; i < 6; i++) {
                    bool dup = false;
                    for (int q = 0; q < i; q++)
                        if (P[q][0] == P[i][0] && P[q][1] == P[i][1] && P[q][2] == P[i][2]) dup = true;
                    if (dup) continue;
                    int p0 = P[i][0], p1 = P[i][1], p2 = P[i][2];
                    if (j < 23) {
                        val += U3_0e[((p0 * L + p1) * L + p2) * 23 + j];
                    } else {
                        int w = (j - 23) / 33, k = (j - 23) % 33;
                        val += U3_1o[(((w * L + p0) * L + p1) * L + p2) * 33 + k];
                    }
                }
            }
        }
        __nv_bfloat16 hv = __float2bfloat16(val);
        float hf = __bfloat162float(hv);
        __nv_bfloat16 lv = __float2bfloat16(val - hf);
        int chunk = t >> 6, t_in = t & 63;
        g_B3hi[chunk * 8192 + j * 64 + t_in] = hv;
        g_B3lo[chunk * 8192 + j * 64 + t_in] = lv;
    } else if (blk < NT3P + NT2) {
        int t = blk - NT3P;
        int rem = t, A = 0, B = 0;
        {
            int i = 0;
            for (;;) { int cnt = L - i;
                       if (rem < cnt) break; rem -= cnt; i++; }
            A = i; B = A + rem;
        }
        if (j == 0) g_idx2[t] = (unsigned)A | ((unsigned)B << 8);
        if (j >= COLS2) return;
        float val = 0.f;
        if (j < 22) {
            if (j < 4) {
                val = U2_0e[(A * L + B) * 4 + j];
                if (A != B) val += U2_0e[(B * L + A) * 4 + j];
            } else {
                int w = (j - 4) / 6, k = (j - 4) % 6;
                val = U2_1o[((w * L + A) * L + B) * 6 + k];
                if (A != B) val += U2_1o[((w * L + B) * L + A) * 6 + k];
            }
        }
        g_Us2[t * COLS2 + j] = val;
    } else {
        if (j >= L * 4) return;
        int a = j >> 2, col = j & 3;
        g_Us1[a * 4 + col] = (col == 0) ? U1_0e[a] : U1_1o[(col - 1) * L + a];
    }
}

// ---------------- K1: wy + order-1/2 + output base (unchanged, passing) ----
__global__ void __launch_bounds__(256) k_wy(
        const float* __restrict__ y, const float* __restrict__ x,
        const float* __restrict__ w3_0e, const float* __restrict__ w3_1o,
        const float* __restrict__ w2_0e, const float* __restrict__ w2_1o,
        const float* __restrict__ w1_0e, const float* __restrict__ w1_1o,
        float* __restrict__ out) {
    __shared__ __align__(16) float ys[NE];
    __shared__ __align__(16) float Xs[NC * 17];
    __shared__ __align__(16) float wys[12 * NC];
    __shared__ __align__(16) float Us2s[NT2 * COLS2];
    __shared__ __align__(16) float Us1s[L * 4];
    __shared__ __align__(16) float red2[NC * 4 * 2];
    const int tid = threadIdx.x;
    const int b = blockIdx.x;

    if (tid < NE) ys[tid] = y[b * NE + tid];
    if (tid < L * 4) Us1s[tid] = g_Us1[tid];
    {
        int c = tid >> 1, off = (tid & 1) * 8;
        const float4* xp = (const float4*)(x + (b * NC + c) * L + off);
        float4 v0 = xp[0], v1 = xp[1];
        float* dst = Xs + c * 17 + off;
        dst[0] = v0.x; dst[1] = v0.y; dst[2] = v0.z; dst[3] = v0.w;
        dst[4] = v1.x; dst[5] = v1.y; dst[6] = v1.z; dst[7] = v1.w;
    }
    for (int i = tid; i < NT2 * (COLS2 / 4); i += 256)
        ((float4*)Us2s)[i] = ((const float4*)g_Us2)[i];
    __syncthreads();

    for (int idx = tid; idx < NWY * NC; idx += 256) {
        int jw = idx >> 7, c = idx & 127;
        const float* wsrc; int K, k;
        if (jw < 23)       { wsrc = w3_0e; K = 23; k = jw; }
        else if (jw < 56)  { wsrc = w3_1o; K = 33; k = jw - 23; }
        else if (jw < 60)  { wsrc = w2_0e; K = 4;  k = jw - 56; }
        else if (jw < 66)  { wsrc = w2_1o; K = 6;  k = jw - 60; }
        else if (jw == 66) { wsrc = w1_0e; K = 1;  k = 0; }
        else               { wsrc = w1_1o; K = 1;  k = 0; }
        float acc = 0.f;
#pragma unroll
        for (int e = 0; e < NE; e++)
            acc = fmaf(wsrc[(e * K + k) * NC + c], ys[e], acc);
        g_wy[(b * NWY + jw) * NC + c] = acc;
        if (jw >= 56) wys[(jw - 56) * NC + c] = acc;
    }
    __syncthreads();

    const int c = tid & 127;
    const int half = tid >> 7;
    const float* Xc = Xs + c * 17;
    ull P2[11];
#pragma unroll
    for (int k = 0; k < 11; k++) P2[k] = 0ull;
    for (int t = half * 68; t < half * 68 + 68; t++) {
        unsigned u = g_idx2[t];
        ull m2 = pack2(Xc[u & 255] * Xc[(u >> 8) & 255]);
        const ull* row = (const ull*)(Us2s + t * COLS2);
#pragma unroll
        for (int k = 0; k < 11; k++) fma2(P2[k], m2, row[k]);
    }
    float contrib[4] = {0.f, 0.f, 0.f, 0.f};
#pragma unroll
    for (int k = 0; k < 11; k++) {
        float lo, hi;
        unpack2(P2[k], lo, hi);
#pragma unroll
        for (int hh = 0; hh < 2; hh++) {
            int j = 2 * k + hh;
            float v = (hh == 0) ? lo : hi;
            int tgt, row;
            if (j < 4) { tgt = 0; row = j; }
            else { int wq = (j - 4) / 6; tgt = 1 + wq; row = 4 + (j - 4 - wq * 6); }
            contrib[tgt] += v * wys[row * NC + c];
        }
    }
    if (half == 0) {
        float P0 = 0.f, P1 = 0.f, Pq = 0.f, P3 = 0.f;
#pragma unroll
        for (int a = 0; a < L; a++) {
            float xa = Xc[a];
            P0 = fmaf(Us1s[a * 4 + 0], xa, P0);
            P1 = fmaf(Us1s[a * 4 + 1], xa, P1);
            Pq = fmaf(Us1s[a * 4 + 2], xa, Pq);
            P3 = fmaf(Us1s[a * 4 + 3], xa, P3);
        }
        contrib[0] = fmaf(P0, wys[10 * NC + c], contrib[0]);
        contrib[1] = fmaf(P1, wys[11 * NC + c], contrib[1]);
        contrib[2] = fmaf(Pq, wys[11 * NC + c], contrib[2]);
        contrib[3] = fmaf(P3, wys[11 * NC + c], contrib[3]);
    }
#pragma unroll
    for (int tgt = 0; tgt < 4; tgt++)
        red2[(c * 4 + tgt) * 2 + half] = contrib[tgt];
    __syncthreads();
    for (int i = tid; i < 512; i += 256) {
        int cc = i >> 2, tgt = i & 3;
        float v = red2[i * 2] + red2[i * 2 + 1];
        if (tgt == 0) out[b * 512 + cc] = v;
        else out[b * 512 + 128 + 3 * cc + (tgt - 1)] = v;
    }
}

// ---------------- K2: order-3 HMMA, K split across 2 blocks/atom ----------
// grid = 256: (atom b, K-half kh). 256 threads = 8 warps; warp owns 16 rows.
// smem: Ah 16K | Al 16K | Bh 16K | Bl 16K | Xs 8.5K | idx 3.3K  = ~77.5KB
#define OFF_AH   0
#define OFF_AL   16384
#define OFF_BH   32768
#define OFF_BL   49152
#define OFF_XS   65536
#define OFF_IDX  74240
#define SMEM_TOTAL 77568

__global__ void __launch_bounds__(256, 2) k_main(const float* __restrict__ x,
                                                 float* __restrict__ out) {
    extern __shared__ __align__(1024) char smc[];
    const uint32_t sb = smem_u32(smc);
    const int tid = threadIdx.x;
    const int wid = tid >> 5;
    const int lane = tid & 31;
    const int b = blockIdx.x >> 1;
    const int kh = blockIdx.x & 1;
    const int q0 = kh ? 7 : 0;
    const int q1 = kh ? NCHUNK : 7;

    float* Xs = (float*)(smc + OFF_XS);
    unsigned* sIdx = (unsigned*)(smc + OFF_IDX);

    // stage X (padded) and idx table
    {
        int c = tid >> 1, off = (tid & 1) * 8;
        const float4* xp = (const float4*)(x + (b * NC + c) * L + off);
        float4 v0 = xp[0], v1 = xp[1];
        float* dst = Xs + c * 17 + off;
        dst[0] = v0.x; dst[1] = v0.y; dst[2] = v0.z; dst[3] = v0.w;
        dst[4] = v1.x; dst[5] = v1.y; dst[6] = v1.z; dst[7] = v1.w;
    }
    for (int i = tid; i < NT3; i += 256) sIdx[i] = g_idx3[i];
    __syncthreads();

    float acc[16][4];
#pragma unroll
    for (int nt = 0; nt < 16; nt++)
#pragma unroll
        for (int k = 0; k < 4; k++) acc[nt][k] = 0.f;

    const int r0 = wid * 16;
    const int mat = lane >> 3, lr = lane & 7;

    for (int q = q0; q < q1; q++) {
        // stage B chunk (row-major global -> XOR-swizzled smem)
        {
            const uint4* sh = (const uint4*)g_B3hi + q * 1024;
            const uint4* sl = (const uint4*)g_B3lo + q * 1024;
            for (int i = tid; i < 1024; i += 256) {
                int row = i >> 3, u = i & 7;
                uint32_t doff = (uint32_t)(row * 128 + ((u ^ (row & 7)) << 4));
                *(uint4*)(smc + OFF_BH + doff) = sh[i];
                *(uint4*)(smc + OFF_BL + doff) = sl[i];
            }
        }
        // build A chunk: monomials, bf16 split, XOR-swizzled store
        for (int item = tid; item < 1024; item += 256) {
            int c = item & 127, u = item >> 7;
            const float* Xc = Xs + c * 17;
            float m[8];
#pragma unroll
            for (int e = 0; e < 8; e++) {
                int gt = q * 64 + u * 8 + e;
                if (gt < NT3) {
                    unsigned uu = sIdx[gt];
                    m[e] = Xc[uu & 255] * Xc[(uu >> 8) & 255] * Xc[(uu >> 16) & 255];
                } else m[e] = 0.f;
            }
            uint32_t hi[4], lo[4];
#pragma unroll
            for (int p = 0; p < 4; p++) {
                uint32_t hp = cvt_bf16x2(m[2 * p], m[2 * p + 1]);
                float h0 = __uint_as_float(hp << 16);
                float h1 = __uint_as_float(hp & 0xffff0000u);
                lo[p] = cvt_bf16x2(m[2 * p] - h0, m[2 * p + 1] - h1);
                hi[p] = hp;
            }
            uint32_t doff = (uint32_t)(c * 128 + ((u ^ (c & 7)) << 4));
            *(uint4*)(smc + OFF_AH + doff) = make_uint4(hi[0], hi[1], hi[2], hi[3]);
            *(uint4*)(smc + OFF_AL + doff) = make_uint4(lo[0], lo[1], lo[2], lo[3]);
        }
        __syncthreads();

        // compute: 4 k-steps x 8 B-pairs x (hi*hi + hi*lo + lo*hi)
#pragma unroll
        for (int s = 0; s < 4; s++) {
            const int u0 = s * 2;
            int arow = r0 + lr + (mat & 1) * 8;
            int au = u0 + (mat >> 1);
            uint32_t aoff = (uint32_t)(arow * 128 + ((au ^ (arow & 7)) << 4));
            uint32_t ah[4], al[4];
            ldsm4(ah, sb + OFF_AH + aoff);
            ldsm4(al, sb + OFF_AL + aoff);
#pragma unroll
            for (int p = 0; p < 8; p++) {
                int brow = p * 16 + (mat >> 1) * 8 + lr;
                int bu = u0 + (mat & 1);
                uint32_t boff = (uint32_t)(brow * 128 + ((bu ^ (brow & 7)) << 4));
                uint32_t bh[4], bl[4];
                ldsm4(bh, sb + OFF_BH + boff);
                ldsm4(bl, sb + OFF_BL + boff);
                mma16816(acc[2 * p],     ah, bh[0], bh[1]);
                mma16816(acc[2 * p],     ah, bl[0], bl[1]);
                mma16816(acc[2 * p],     al, bh[0], bh[1]);
                mma16816(acc[2 * p + 1], ah, bh[2], bh[3]);
                mma16816(acc[2 * p + 1], ah, bl[2], bl[3]);
                mma16816(acc[2 * p + 1], al, bh[2], bh[3]);
            }
        }
        __syncthreads();   // buffers reused next chunk
    }

    // ===== epilogue: weight by wy (LDG, L1-cached), quad-reduce, atomicAdd =====
    const float* wyb = g_wy + b * NWY * NC;
    const int r1 = r0 + (lane >> 2);
    float ct0[4] = {0.f, 0.f, 0.f, 0.f};
    float ct1[4] = {0.f, 0.f, 0.f, 0.f};
#pragma unroll
    for (int nt = 0; nt < 16; nt++) {
#pragma unroll
        for (int hh = 0; hh < 2; hh++) {
            int j = nt * 8 + 2 * (lane & 3) + hh;
            if (j < 122) {
                int tgt, wyc;
                if (j < 23) { tgt = 0; wyc = j; }
                else { int wq = (j - 23) / 33; tgt = 1 + wq; wyc = 23 + (j - 23 - wq * 33); }
                ct0[tgt] += acc[nt][hh]     * wyb[wyc * NC + r1];
                ct1[tgt] += acc[nt][2 + hh] * wyb[wyc * NC + r1 + 8];
            }
        }
    }
#pragma unroll
    for (int t = 0; t < 4; t++) {
        ct0[t] += __shfl_xor_sync(0xffffffffu, ct0[t], 1);
        ct0[t] += __shfl_xor_sync(0xffffffffu, ct0[t], 2);
        ct1[t] += __shfl_xor_sync(0xffffffffu, ct1[t], 1);
        ct1[t] += __shfl_xor_sync(0xffffffffu, ct1[t], 2);
    }
    if ((lane & 3) == 0) {
        float* ob = out + b * 512;
        int ra = r1, rb = r1 + 8;
        atomicAdd(&ob[ra], ct0[0]);
        atomicAdd(&ob[128 + 3 * ra + 0], ct0[1]);
        atomicAdd(&ob[128 + 3 * ra + 1], ct0[2]);
        atomicAdd(&ob[128 + 3 * ra + 2], ct0[3]);
        atomicAdd(&ob[rb], ct1[0]);
        atomicAdd(&ob[128 + 3 * rb + 0], ct1[1]);
        atomicAdd(&ob[128 + 3 * rb + 1], ct1[2]);
        atomicAdd(&ob[128 + 3 * rb + 2], ct1[3]);
    }
}

extern "C" void kernel_launch(void* const* d_in, const int* in_sizes, int n_in,
                              void* d_out, int out_size) {
    const float* x      = (const float*)d_in[0];
    const float* y      = (const float*)d_in[1];
    const float* U1_0e  = (const float*)d_in[2];
    const float* U2_0e  = (const float*)d_in[3];
    const float* U3_0e  = (const float*)d_in[4];
    const float* U1_1o  = (const float*)d_in[5];
    const float* U2_1o  = (const float*)d_in[6];
    const float* U3_1o  = (const float*)d_in[7];
    const float* w1_0e  = (const float*)d_in[8];
    const float* w2_0e  = (const float*)d_in[9];
    const float* w3_0e  = (const float*)d_in[10];
    const float* w1_1o  = (const float*)d_in[11];
    const float* w2_1o  = (const float*)d_in[12];
    const float* w3_1o  = (const float*)d_in[13];
    float* out = (float*)d_out;

    cudaFuncSetAttribute(k_main, cudaFuncAttributeMaxDynamicSharedMemorySize, SMEM_TOTAL);

    k_setup<<<NT3P + NT2 + 1, 128>>>(U1_0e, U2_0e, U3_0e, U1_1o, U2_1o, U3_1o);
    k_wy<<<NB, 256>>>(y, x, w3_0e, w3_1o, w2_0e, w2_1o, w1_0e, w1_1o, out);
    k_main<<<2 * NB, 256, SMEM_TOTAL>>>(x, out);
}

// round 10
// speedup vs baseline: 2.6295x; 1.1750x over previous
#include <cuda_runtime.h>
#include <cuda_fp16.h>
#include <cstdint>

#define L    16
#define NB   128
#define NC   128
#define NE   10
#define NT3  816
#define NT3P 832      // padded to 13*64
#define NT2  136
#define COLS2 24
#define NWY  68
#define NCHUNK 13     // K chunks of 64

typedef unsigned long long ull;

// ---------------- device globals ----------------
__device__ unsigned g_idx3[NT3];
__device__ unsigned g_idx2[NT2];
__device__ float    g_Us2[NT2 * COLS2];
__device__ float    g_Us1[L * 4];
__device__ float    g_wy[NB * NWY * NC];
// split-fp16 coefficient chunk images, row-major: [chunk][j=128][t_in=64]
__device__ __align__(16) __half g_B3hi[NCHUNK * 8192];
__device__ __align__(16) __half g_B3lo[NCHUNK * 8192];

// ---------------- helpers ----------------
__device__ __forceinline__ uint32_t smem_u32(const void* p) {
    uint32_t a;
    asm("{ .reg .u64 t; cvta.to.shared.u64 t, %1; cvt.u32.u64 %0, t; }" : "=r"(a) : "l"(p));
    return a;
}
__device__ __forceinline__ ull pack2(float v) {
    ull r; asm("mov.b64 %0, {%1, %1};" : "=l"(r) : "f"(v)); return r;
}
__device__ __forceinline__ void unpack2(ull v, float& lo, float& hi) {
    asm("mov.b64 {%0, %1}, %2;" : "=f"(lo), "=f"(hi) : "l"(v));
}
__device__ __forceinline__ void fma2(ull& d, ull a, ull b) {
    asm("fma.rn.f32x2 %0, %1, %2, %0;" : "+l"(d) : "l"(a), "l"(b));
}
__device__ __forceinline__ void ldsm4(uint32_t* r, uint32_t addr) {
    asm volatile("ldmatrix.sync.aligned.m8n8.x4.shared.b16 {%0,%1,%2,%3}, [%4];"
                 : "=r"(r[0]), "=r"(r[1]), "=r"(r[2]), "=r"(r[3]) : "r"(addr));
}
__device__ __forceinline__ void mma16816h(float* d, const uint32_t* a,
                                          uint32_t b0, uint32_t b1) {
    asm volatile("mma.sync.aligned.m16n8k16.row.col.f32.f16.f16.f32 "
                 "{%0,%1,%2,%3}, {%4,%5,%6,%7}, {%8,%9}, {%0,%1,%2,%3};"
                 : "+f"(d[0]), "+f"(d[1]), "+f"(d[2]), "+f"(d[3])
                 : "r"(a[0]), "r"(a[1]), "r"(a[2]), "r"(a[3]), "r"(b0), "r"(b1));
}
__device__ __forceinline__ void cp16(uint32_t daddr, const void* gsrc) {
    asm volatile("cp.async.cg.shared.global [%0], [%1], 16;"
                 :: "r"(daddr), "l"(gsrc) : "memory");
}
#define CP_COMMIT() asm volatile("cp.async.commit_group;" ::: "memory")

// ---------------- K0: symmetrize + fp16-split ----------------
__global__ void k_setup(const float* __restrict__ U1_0e, const float* __restrict__ U2_0e,
                        const float* __restrict__ U3_0e, const float* __restrict__ U1_1o,
                        const float* __restrict__ U2_1o, const float* __restrict__ U3_1o) {
    int blk = blockIdx.x;
    int j = threadIdx.x;
    if (blk < NT3P) {
        int t = blk;
        float val = 0.f;
        if (t < NT3) {
            int rem = t, A = 0, B = 0, D = 0;
            {
                int i = 0;
                for (;;) { int m = L - i; int cnt = m * (m + 1) / 2;
                           if (rem < cnt) break; rem -= cnt; i++; }
                A = i;
                int q = A;
                for (;;) { int cnt = L - q;
                           if (rem < cnt) break; rem -= cnt; q++; }
                B = q; D = B + rem;
            }
            if (j == 0) g_idx3[t] = (unsigned)A | ((unsigned)B << 8) | ((unsigned)D << 16);
            int P[6][3] = {{A,B,D},{A,D,B},{B,A,D},{B,D,A},{D,A,B},{D,B,A}};
            if (j < 122) {
                for (int i = 0; i < 6; i++) {
                    bool dup = false;
                    for (int q = 0; q < i; q++)
                        if (P[q][0] == P[i][0] && P[q][1] == P[i][1] && P[q][2] == P[i][2]) dup = true;
                    if (dup) continue;
                    int p0 = P[i][0], p1 = P[i][1], p2 = P[i][2];
                    if (j < 23) {
                        val += U3_0e[((p0 * L + p1) * L + p2) * 23 + j];
                    } else {
                        int w = (j - 23) / 33, k = (j - 23) % 33;
                        val += U3_1o[(((w * L + p0) * L + p1) * L + p2) * 33 + k];
                    }
                }
            }
        }
        __half hv = __float2half_rn(val);
        __half lv = __float2half_rn(val - __half2float(hv));
        int chunk = t >> 6, t_in = t & 63;
        g_B3hi[chunk * 8192 + j * 64 + t_in] = hv;
        g_B3lo[chunk * 8192 + j * 64 + t_in] = lv;
    } else if (blk < NT3P + NT2) {
        int t = blk - NT3P;
        int rem = t, A = 0, B = 0;
        {
            int i = 0;
            for (;;) { int cnt = L - i;
                       if (rem < cnt) break; rem -= cnt; i++; }
            A = i; B = A + rem;
        }
        if (j == 0) g_idx2[t] = (unsigned)A | ((unsigned)B << 8);
        if (j >= COLS2) return;
        float val = 0.f;
        if (j < 22) {
            if (j < 4) {
                val = U2_0e[(A * L + B) * 4 + j];
                if (A != B) val += U2_0e[(B * L + A) * 4 + j];
            } else {
                int w = (j - 4) / 6, k = (j - 4) % 6;
                val = U2_1o[((w * L + A) * L + B) * 6 + k];
                if (A != B) val += U2_1o[((w * L + B) * L + A) * 6 + k];
            }
        }
        g_Us2[t * COLS2 + j] = val;
    } else {
        if (j >= L * 4) return;
        int a = j >> 2, col = j & 3;
        g_Us1[a * 4 + col] = (col == 0) ? U1_0e[a] : U1_1o[(col - 1) * L + a];
    }
}

// ---------------- K1: wy + order-1/2 + output base (unchanged, passing) ----
__global__ void __launch_bounds__(256) k_wy(
        const float* __restrict__ y, const float* __restrict__ x,
        const float* __restrict__ w3_0e, const float* __restrict__ w3_1o,
        const float* __restrict__ w2_0e, const float* __restrict__ w2_1o,
        const float* __restrict__ w1_0e, const float* __restrict__ w1_1o,
        float* __restrict__ out) {
    __shared__ __align__(16) float ys[NE];
    __shared__ __align__(16) float Xs[NC * 17];
    __shared__ __align__(16) float wys[12 * NC];
    __shared__ __align__(16) float Us2s[NT2 * COLS2];
    __shared__ __align__(16) float Us1s[L * 4];
    __shared__ __align__(16) float red2[NC * 4 * 2];
    const int tid = threadIdx.x;
    const int b = blockIdx.x;

    if (tid < NE) ys[tid] = y[b * NE + tid];
    if (tid < L * 4) Us1s[tid] = g_Us1[tid];
    {
        int c = tid >> 1, off = (tid & 1) * 8;
        const float4* xp = (const float4*)(x + (b * NC + c) * L + off);
        float4 v0 = xp[0], v1 = xp[1];
        float* dst = Xs + c * 17 + off;
        dst[0] = v0.x; dst[1] = v0.y; dst[2] = v0.z; dst[3] = v0.w;
        dst[4] = v1.x; dst[5] = v1.y; dst[6] = v1.z; dst[7] = v1.w;
    }
    for (int i = tid; i < NT2 * (COLS2 / 4); i += 256)
        ((float4*)Us2s)[i] = ((const float4*)g_Us2)[i];
    __syncthreads();

    for (int idx = tid; idx < NWY * NC; idx += 256) {
        int jw = idx >> 7, c = idx & 127;
        const float* wsrc; int K, k;
        if (jw < 23)       { wsrc = w3_0e; K = 23; k = jw; }
        else if (jw < 56)  { wsrc = w3_1o; K = 33; k = jw - 23; }
        else if (jw < 60)  { wsrc = w2_0e; K = 4;  k = jw - 56; }
        else if (jw < 66)  { wsrc = w2_1o; K = 6;  k = jw - 60; }
        else if (jw == 66) { wsrc = w1_0e; K = 1;  k = 0; }
        else               { wsrc = w1_1o; K = 1;  k = 0; }
        float acc = 0.f;
#pragma unroll
        for (int e = 0; e < NE; e++)
            acc = fmaf(wsrc[(e * K + k) * NC + c], ys[e], acc);
        g_wy[(b * NWY + jw) * NC + c] = acc;
        if (jw >= 56) wys[(jw - 56) * NC + c] = acc;
    }
    __syncthreads();

    const int c = tid & 127;
    const int half = tid >> 7;
    const float* Xc = Xs + c * 17;
    ull P2[11];
#pragma unroll
    for (int k = 0; k < 11; k++) P2[k] = 0ull;
    for (int t = half * 68; t < half * 68 + 68; t++) {
        unsigned u = g_idx2[t];
        ull m2 = pack2(Xc[u & 255] * Xc[(u >> 8) & 255]);
        const ull* row = (const ull*)(Us2s + t * COLS2);
#pragma unroll
        for (int k = 0; k < 11; k++) fma2(P2[k], m2, row[k]);
    }
    float contrib[4] = {0.f, 0.f, 0.f, 0.f};
#pragma unroll
    for (int k = 0; k < 11; k++) {
        float lo, hi;
        unpack2(P2[k], lo, hi);
#pragma unroll
        for (int hh = 0; hh < 2; hh++) {
            int j = 2 * k + hh;
            float v = (hh == 0) ? lo : hi;
            int tgt, row;
            if (j < 4) { tgt = 0; row = j; }
            else { int wq = (j - 4) / 6; tgt = 1 + wq; row = 4 + (j - 4 - wq * 6); }
            contrib[tgt] += v * wys[row * NC + c];
        }
    }
    if (half == 0) {
        float P0 = 0.f, P1 = 0.f, Pq = 0.f, P3 = 0.f;
#pragma unroll
        for (int a = 0; a < L; a++) {
            float xa = Xc[a];
            P0 = fmaf(Us1s[a * 4 + 0], xa, P0);
            P1 = fmaf(Us1s[a * 4 + 1], xa, P1);
            Pq = fmaf(Us1s[a * 4 + 2], xa, Pq);
            P3 = fmaf(Us1s[a * 4 + 3], xa, P3);
        }
        contrib[0] = fmaf(P0, wys[10 * NC + c], contrib[0]);
        contrib[1] = fmaf(P1, wys[11 * NC + c], contrib[1]);
        contrib[2] = fmaf(Pq, wys[11 * NC + c], contrib[2]);
        contrib[3] = fmaf(P3, wys[11 * NC + c], contrib[3]);
    }
#pragma unroll
    for (int tgt = 0; tgt < 4; tgt++)
        red2[(c * 4 + tgt) * 2 + half] = contrib[tgt];
    __syncthreads();
    for (int i = tid; i < 512; i += 256) {
        int cc = i >> 2, tgt = i & 3;
        float v = red2[i * 2] + red2[i * 2 + 1];
        if (tgt == 0) out[b * 512 + cc] = v;
        else out[b * 512 + 128 + 3 * cc + (tgt - 1)] = v;
    }
}

// ---------------- K2: order-3 HMMA fp16, cp.async pipelined ----------------
// grid = 256: (atom b, K-half kh). 8 warps = 4 row-groups x 2 col-groups.
// smem: A 16K | B0 32K | B1 32K | Xs 8.5K | red 4K | idx 3.3K  = ~96K
#define OFF_A    0
#define OFF_B0   16384
#define OFF_B1   49152
#define OFF_XS   81920
#define OFF_RED  90624
#define OFF_IDX  94720
#define SMEM_TOTAL 98048

__global__ void __launch_bounds__(256, 2) k_main(const float* __restrict__ x,
                                                 float* __restrict__ out) {
    extern __shared__ __align__(1024) char smc[];
    const uint32_t sb = smem_u32(smc);
    const int tid = threadIdx.x;
    const int wid = tid >> 5;
    const int lane = tid & 31;
    const int b = blockIdx.x >> 1;
    const int kh = blockIdx.x & 1;
    const int q0 = kh ? 7 : 0;
    const int q1 = kh ? NCHUNK : 7;

    float* Xs = (float*)(smc + OFF_XS);
    float* red = (float*)(smc + OFF_RED);      // [2][128][4]
    unsigned* sIdx = (unsigned*)(smc + OFF_IDX);

    // prologue: start streaming B(q0) immediately
    {
        const char* srcH = (const char*)g_B3hi + q0 * 16384;
        const char* srcL = (const char*)g_B3lo + q0 * 16384;
        for (int i = tid; i < 1024; i += 256) {
            int row = i >> 3, u = i & 7;
            uint32_t doff = (uint32_t)(row * 128 + ((u ^ (row & 7)) << 4));
            int soff = (row * 64 + u * 8) * 2;
            cp16(sb + OFF_B0 + doff, srcH + soff);
            cp16(sb + OFF_B0 + 16384 + doff, srcL + soff);
        }
        CP_COMMIT();
    }

    // stage X (padded) and idx table
    {
        int c = tid >> 1, off = (tid & 1) * 8;
        const float4* xp = (const float4*)(x + (b * NC + c) * L + off);
        float4 v0 = xp[0], v1 = xp[1];
        float* dst = Xs + c * 17 + off;
        dst[0] = v0.x; dst[1] = v0.y; dst[2] = v0.z; dst[3] = v0.w;
        dst[4] = v1.x; dst[5] = v1.y; dst[6] = v1.z; dst[7] = v1.w;
    }
    for (int i = tid; i < NT3; i += 256) sIdx[i] = g_idx3[i];
    __syncthreads();

    float acc[16][4];
#pragma unroll
    for (int nt = 0; nt < 16; nt++)
#pragma unroll
        for (int k = 0; k < 4; k++) acc[nt][k] = 0.f;

    const int rw = wid & 3, cw = wid >> 2;
    const int R0 = rw * 32, C0 = cw * 64;
    const int mat = lane >> 3, lr = lane & 7;
    const int g = lane >> 2;

    for (int q = q0; q < q1; q++) {
        const uint32_t bufB = (((q - q0) & 1) ? OFF_B1 : OFF_B0);
        const uint32_t nxtB = (((q - q0) & 1) ? OFF_B0 : OFF_B1);

        // build A(q): monomials -> fp16, XOR-swizzled store
        for (int item = tid; item < 1024; item += 256) {
            int c = item & 127, u = item >> 7;
            const float* Xc = Xs + c * 17;
            float m[8];
#pragma unroll
            for (int e = 0; e < 8; e++) {
                int gt = q * 64 + u * 8 + e;
                if (gt < NT3) {
                    unsigned uu = sIdx[gt];
                    m[e] = Xc[uu & 255] * Xc[(uu >> 8) & 255] * Xc[(uu >> 16) & 255];
                } else m[e] = 0.f;
            }
            uint32_t h[4];
#pragma unroll
            for (int p = 0; p < 4; p++) {
                __half2 hp = __floats2half2_rn(m[2 * p], m[2 * p + 1]);
                h[p] = *(uint32_t*)&hp;
            }
            uint32_t doff = (uint32_t)(c * 128 + ((u ^ (c & 7)) << 4));
            *(uint4*)(smc + OFF_A + doff) = make_uint4(h[0], h[1], h[2], h[3]);
        }

        // stream B(q+1) into the other buffer
        if (q + 1 < q1) {
            const char* srcH = (const char*)g_B3hi + (q + 1) * 16384;
            const char* srcL = (const char*)g_B3lo + (q + 1) * 16384;
            for (int i = tid; i < 1024; i += 256) {
                int row = i >> 3, u = i & 7;
                uint32_t doff = (uint32_t)(row * 128 + ((u ^ (row & 7)) << 4));
                int soff = (row * 64 + u * 8) * 2;
                cp16(sb + nxtB + doff, srcH + soff);
                cp16(sb + nxtB + 16384 + doff, srcL + soff);
            }
            CP_COMMIT();
            asm volatile("cp.async.wait_group 1;" ::: "memory");
        } else {
            asm volatile("cp.async.wait_group 0;" ::: "memory");
        }
        __syncthreads();

        // MMA: 4 k-steps; warp tile 32 rows x 64 cols; 2 terms (B hi + lo)
#pragma unroll
        for (int s = 0; s < 4; s++) {
            const int u0 = s * 2;
            uint32_t ah0[4], ah1[4];
            {
                int arow = R0 + lr + (mat & 1) * 8;
                int au = u0 + (mat >> 1);
                ldsm4(ah0, sb + OFF_A + (uint32_t)(arow * 128 + ((au ^ (arow & 7)) << 4)));
                int arow1 = arow + 16;
                ldsm4(ah1, sb + OFF_A + (uint32_t)(arow1 * 128 + ((au ^ (arow1 & 7)) << 4)));
            }
#pragma unroll
            for (int p = 0; p < 4; p++) {
                int brow = C0 + p * 16 + (mat >> 1) * 8 + lr;
                int bu = u0 + (mat & 1);
                uint32_t boff = (uint32_t)(brow * 128 + ((bu ^ (brow & 7)) << 4));
                uint32_t bh[4], bl[4];
                ldsm4(bh, sb + bufB + boff);
                ldsm4(bl, sb + bufB + 16384 + boff);
                mma16816h(acc[p * 2],         ah0, bh[0], bh[1]);
                mma16816h(acc[p * 2],         ah0, bl[0], bl[1]);
                mma16816h(acc[p * 2 + 1],     ah0, bh[2], bh[3]);
                mma16816h(acc[p * 2 + 1],     ah0, bl[2], bl[3]);
                mma16816h(acc[8 + p * 2],     ah1, bh[0], bh[1]);
                mma16816h(acc[8 + p * 2],     ah1, bl[0], bl[1]);
                mma16816h(acc[8 + p * 2 + 1], ah1, bh[2], bh[3]);
                mma16816h(acc[8 + p * 2 + 1], ah1, bl[2], bl[3]);
            }
        }
        __syncthreads();   // A buffer reused next chunk
    }

    // ===== epilogue: weight by wy, reduce cols (shfl) + col-groups (smem) ====
    const float* wyb = g_wy + b * NWY * NC;
    float ct[4][4];    // [rowslot: mi*2 + (0:+0, 1:+8)][tgt]
#pragma unroll
    for (int a = 0; a < 4; a++)
#pragma unroll
        for (int t = 0; t < 4; t++) ct[a][t] = 0.f;
#pragma unroll
    for (int mi = 0; mi < 2; mi++) {
        int ra = R0 + mi * 16 + g;
        int rb = ra + 8;
#pragma unroll
        for (int ni = 0; ni < 8; ni++) {
#pragma unroll
            for (int hh = 0; hh < 2; hh++) {
                int j = C0 + ni * 8 + 2 * (lane & 3) + hh;
                if (j < 122) {
                    int tgt, wyc;
                    if (j < 23) { tgt = 0; wyc = j; }
                    else { int wq = (j - 23) / 33; tgt = 1 + wq; wyc = 23 + (j - 23 - wq * 33); }
                    ct[mi * 2 + 0][tgt] += acc[mi * 8 + ni][hh]     * wyb[wyc * NC + ra];
                    ct[mi * 2 + 1][tgt] += acc[mi * 8 + ni][2 + hh] * wyb[wyc * NC + rb];
                }
            }
        }
    }
#pragma unroll
    for (int a = 0; a < 4; a++)
#pragma unroll
        for (int t = 0; t < 4; t++) {
            ct[a][t] += __shfl_xor_sync(0xffffffffu, ct[a][t], 1);
            ct[a][t] += __shfl_xor_sync(0xffffffffu, ct[a][t], 2);
        }
    if ((lane & 3) == 0) {
#pragma unroll
        for (int mi = 0; mi < 2; mi++) {
            int ra = R0 + mi * 16 + g;
#pragma unroll
            for (int t = 0; t < 4; t++) {
                red[(cw * 128 + ra) * 4 + t]     = ct[mi * 2 + 0][t];
                red[(cw * 128 + ra + 8) * 4 + t] = ct[mi * 2 + 1][t];
            }
        }
    }
    __syncthreads();
    for (int i = tid; i < 512; i += 256) {
        int row = i >> 2, tgt = i & 3;
        float v = red[row * 4 + tgt] + red[(128 + row) * 4 + tgt];
        float* ob = out + b * 512;
        if (tgt == 0) atomicAdd(&ob[row], v);
        else atomicAdd(&ob[128 + 3 * row + (tgt - 1)], v);
    }
}

extern "C" void kernel_launch(void* const* d_in, const int* in_sizes, int n_in,
                              void* d_out, int out_size) {
    const float* x      = (const float*)d_in[0];
    const float* y      = (const float*)d_in[1];
    const float* U1_0e  = (const float*)d_in[2];
    const float* U2_0e  = (const float*)d_in[3];
    const float* U3_0e  = (const float*)d_in[4];
    const float* U1_1o  = (const float*)d_in[5];
    const float* U2_1o  = (const float*)d_in[6];
    const float* U3_1o  = (const float*)d_in[7];
    const float* w1_0e  = (const float*)d_in[8];
    const float* w2_0e  = (const float*)d_in[9];
    const float* w3_0e  = (const float*)d_in[10];
    const float* w1_1o  = (const float*)d_in[11];
    const float* w2_1o  = (const float*)d_in[12];
    const float* w3_1o  = (const float*)d_in[13];
    float* out = (float*)d_out;

    cudaFuncSetAttribute(k_main, cudaFuncAttributeMaxDynamicSharedMemorySize, SMEM_TOTAL);

    k_setup<<<NT3P + NT2 + 1, 128>>>(U1_0e, U2_0e, U3_0e, U1_1o, U2_1o, U3_1o);
    k_wy<<<NB, 256>>>(y, x, w3_0e, w3_1o, w2_0e, w2_1o, w1_0e, w1_1o, out);
    k_main<<<2 * NB, 256, SMEM_TOTAL>>>(x, out);
}